// round 6
// baseline (speedup 1.0000x reference)
#include <cuda_runtime.h>
#include <cuda_bf16.h>
#include <math.h>
#include <stdint.h>

#define NT 2048
#define DD 1024
#define CC 768
#define NH 16
#define HD 64
#define MT 2048
#define FF 4096

typedef unsigned short ushortx;

// ---------------- scratch (bf16 pairs stored as ushort) ----------------------
__device__ ushortx g_xqh[NT * DD], g_xql[NT * DD];
__device__ ushortx g_kvh[MT * CC], g_kvl[MT * CC];
__device__ ushortx g_qh[NT * DD], g_ql[NT * DD];
__device__ ushortx g_kh[MT * DD], g_kl[MT * DD];
__device__ ushortx g_vh[MT * DD], g_vl[MT * DD];
__device__ ushortx g_oh[NT * DD], g_ol[NT * DD];
__device__ float   g_x1[NT * DD];
__device__ ushortx g_hlnh[NT * DD], g_hlnl[NT * DD];
__device__ ushortx g_h1h[(size_t)NT * FF], g_h1l[(size_t)NT * FF];
__device__ ushortx g_wqh[DD * DD], g_wql[DD * DD];
__device__ ushortx g_wkh[CC * DD], g_wkl[CC * DD];
__device__ ushortx g_wvh[CC * DD], g_wvl[CC * DD];
__device__ ushortx g_woh[DD * DD], g_wol[DD * DD];
__device__ ushortx g_w1h[(size_t)DD * FF], g_w1l[(size_t)DD * FF];
__device__ ushortx g_w2h[(size_t)FF * DD], g_w2l[(size_t)FF * DD];
__device__ float   g_part[4][(size_t)NT * DD];   // split-K partials

// ---------------- helpers ----------------------------------------------------
__device__ __forceinline__ uint32_t smem_addr_u32(const void* p) {
    uint32_t a;
    asm("{ .reg .u64 t; cvta.to.shared.u64 t, %1; cvt.u32.u64 %0, t; }" : "=r"(a) : "l"(p));
    return a;
}
__device__ __forceinline__ void ldsm4(uint32_t* r, uint32_t addr) {
    asm volatile("ldmatrix.sync.aligned.m8n8.x4.shared.b16 {%0,%1,%2,%3}, [%4];"
                 : "=r"(r[0]), "=r"(r[1]), "=r"(r[2]), "=r"(r[3]) : "r"(addr));
}
__device__ __forceinline__ void ldsm4t(uint32_t* r, uint32_t addr) {
    asm volatile("ldmatrix.sync.aligned.m8n8.x4.trans.shared.b16 {%0,%1,%2,%3}, [%4];"
                 : "=r"(r[0]), "=r"(r[1]), "=r"(r[2]), "=r"(r[3]) : "r"(addr));
}
__device__ __forceinline__ void mma_bf16(float* d, const uint32_t* a, const uint32_t* b) {
    asm volatile(
        "mma.sync.aligned.m16n8k16.row.col.f32.bf16.bf16.f32 "
        "{%0,%1,%2,%3}, {%4,%5,%6,%7}, {%8,%9}, {%0,%1,%2,%3};"
        : "+f"(d[0]), "+f"(d[1]), "+f"(d[2]), "+f"(d[3])
        : "r"(a[0]), "r"(a[1]), "r"(a[2]), "r"(a[3]), "r"(b[0]), "r"(b[1]));
}
__device__ __forceinline__ void split2(float x, float y, uint32_t& h, uint32_t& l) {
    __nv_bfloat16 xh = __float2bfloat16(x), yh = __float2bfloat16(y);
    float xr = x - __bfloat162float(xh);
    float yr = y - __bfloat162float(yh);
    __nv_bfloat16 xl = __float2bfloat16(xr), yl = __float2bfloat16(yr);
    h = (uint32_t)__bfloat16_as_ushort(xh) | ((uint32_t)__bfloat16_as_ushort(yh) << 16);
    l = (uint32_t)__bfloat16_as_ushort(xl) | ((uint32_t)__bfloat16_as_ushort(yl) << 16);
}
__device__ __forceinline__ void cpa16(uint32_t d, const void* g) {
    asm volatile("cp.async.cg.shared.global [%0], [%1], 16;" :: "r"(d), "l"(g));
}
__device__ __forceinline__ void cpcommit() { asm volatile("cp.async.commit_group;" ::: "memory"); }
template <int N>
__device__ __forceinline__ void cpwait() {
    asm volatile("cp.async.wait_group %0;" :: "n"(N) : "memory");
}

// ---------------- fused weight convert ----------------------------------------
__global__ __launch_bounds__(256) void convert_all(
    const float* wq, const float* wk, const float* wv, const float* wo,
    const float* w1, const float* w2,
    ushortx* wqh, ushortx* wql, ushortx* wkh, ushortx* wkl,
    ushortx* wvh, ushortx* wvl, ushortx* woh, ushortx* wol,
    ushortx* w1h, ushortx* w1l, ushortx* w2h, ushortx* w2l) {
    const float* s;
    ushortx *h, *l;
    int n4;
    switch (blockIdx.y) {
        case 0: s = wq; h = wqh; l = wql; n4 = DD * DD / 4; break;
        case 1: s = wk; h = wkh; l = wkl; n4 = CC * DD / 4; break;
        case 2: s = wv; h = wvh; l = wvl; n4 = CC * DD / 4; break;
        case 3: s = wo; h = woh; l = wol; n4 = DD * DD / 4; break;
        case 4: s = w1; h = w1h; l = w1l; n4 = DD * FF / 4; break;
        default: s = w2; h = w2h; l = w2l; n4 = FF * DD / 4; break;
    }
    int i = blockIdx.x * 256 + threadIdx.x;
    if (i >= n4) return;
    float4 f = ((const float4*)s)[i];
    uint32_t h0, l0, h1, l1;
    split2(f.x, f.y, h0, l0);
    split2(f.z, f.w, h1, l1);
    ((uint2*)h)[i] = make_uint2(h0, h1);
    ((uint2*)l)[i] = make_uint2(l0, l1);
}

// ---------------- split-K combine ---------------------------------------------
template <int SPLIT>
__global__ __launch_bounds__(256) void combine_kernel(
    const float* __restrict__ P, const float* __restrict__ bias,
    const float* __restrict__ Res, float* __restrict__ out) {
    int i = blockIdx.x * 256 + threadIdx.x;  // float4 index
    float4 a = ((const float4*)P)[i];
#pragma unroll
    for (int s = 1; s < SPLIT; s++) {
        float4 p = ((const float4*)(P + (size_t)s * NT * DD))[i];
        a.x += p.x; a.y += p.y; a.z += p.z; a.w += p.w;
    }
    int c4 = i & (DD / 4 - 1);
    float4 b = ((const float4*)bias)[c4];
    float4 r = ((const float4*)Res)[i];
    a.x += b.x + r.x; a.y += b.y + r.y; a.z += b.z + r.z; a.w += b.w + r.w;
    ((float4*)out)[i] = a;
}

// ---------------- layernorm -> bf16 pair -------------------------------------
__device__ __forceinline__ float block_reduce_sum(float v) {
    __shared__ float sh[8];
    int tid = threadIdx.x;
#pragma unroll
    for (int o = 16; o > 0; o >>= 1) v += __shfl_down_sync(0xffffffffu, v, o);
    if ((tid & 31) == 0) sh[tid >> 5] = v;
    __syncthreads();
    if (tid < 32) {
        v = (tid < 8) ? sh[tid] : 0.f;
#pragma unroll
        for (int o = 4; o > 0; o >>= 1) v += __shfl_down_sync(0xffffffffu, v, o);
        if (tid == 0) sh[0] = v;
    }
    __syncthreads();
    float r = sh[0];
    __syncthreads();
    return r;
}

template <int DIM>
__global__ __launch_bounds__(256) void ln_pair_kernel(
    const float* __restrict__ x, const float* __restrict__ w, const float* __restrict__ b,
    ushortx* __restrict__ oh, ushortx* __restrict__ ol) {
    const float* xr = x + (size_t)blockIdx.x * DIM;
    int tid = threadIdx.x;
    float4 f = make_float4(0.f, 0.f, 0.f, 0.f);
    if (tid < DIM / 4) f = ((const float4*)xr)[tid];
    float s = f.x + f.y + f.z + f.w;
    float mean = block_reduce_sum(s) * (1.f / DIM);
    float vv = 0.f;
    if (tid < DIM / 4) {
        float c0 = f.x - mean, c1 = f.y - mean, c2 = f.z - mean, c3 = f.w - mean;
        vv = c0 * c0 + c1 * c1 + c2 * c2 + c3 * c3;
    }
    float var = block_reduce_sum(vv) * (1.f / DIM);
    float inv = rsqrtf(var + 1e-12f);
    if (tid < DIM / 4) {
        float4 w4 = ((const float4*)w)[tid];
        float4 b4 = ((const float4*)b)[tid];
        float o0 = (f.x - mean) * inv * w4.x + b4.x;
        float o1 = (f.y - mean) * inv * w4.y + b4.y;
        float o2 = (f.z - mean) * inv * w4.z + b4.z;
        float o3 = (f.w - mean) * inv * w4.w + b4.w;
        uint32_t h0, l0, h1, l1;
        split2(o0, o1, h0, l0);
        split2(o2, o3, h1, l1);
        ((uint2*)(oh + (size_t)blockIdx.x * DIM))[tid] = make_uint2(h0, h1);
        ((uint2*)(ol + (size_t)blockIdx.x * DIM))[tid] = make_uint2(l0, l1);
    }
}

// ---------------- bf16-pair GEMM core -----------------------------------------
template <int BIAS, int RES, int GELU, int OUTPAIR>
__device__ __forceinline__ void gemm_core(
    const ushortx* __restrict__ Ah, const ushortx* __restrict__ Al,
    const ushortx* __restrict__ Bh, const ushortx* __restrict__ Bl,
    const float* __restrict__ bias, const float* __restrict__ Res,
    float* __restrict__ Cf, ushortx* __restrict__ Ch, ushortx* __restrict__ Cl,
    int K, int lda, int ldb, int bx, int by) {
    constexpr int RA = 80, RB = 272;
    constexpr int ASZ = 128 * RA;
    constexpr int BSZ = 32 * RB;
    constexpr int STAGE = 2 * ASZ + 2 * BSZ;  // 37888

    extern __shared__ char sm[];
    const int tid = threadIdx.x, lane = tid & 31, wid = tid >> 5;
    const int wm = wid & 1, wn = wid >> 1;
    const uint32_t sb = smem_addr_u32(sm);

    const ushortx* Abh = Ah + (size_t)by * 128 * lda;
    const ushortx* Abl = Al + (size_t)by * 128 * lda;
    const ushortx* Bbh = Bh + (size_t)bx * 128;
    const ushortx* Bbl = Bl + (size_t)bx * 128;

    auto issue = [&](int k0, int buf) {
        uint32_t d = sb + buf * STAGE;
#pragma unroll
        for (int j = 0; j < 2; j++) {
            int i = tid + j * 256;
            int r = i >> 2, s = i & 3;
            uint32_t dd = d + (uint32_t)(r * RA + s * 16);
            size_t so = (size_t)r * lda + k0 + s * 8;
            cpa16(dd, Abh + so);
            cpa16(dd + ASZ, Abl + so);
        }
#pragma unroll
        for (int j = 0; j < 2; j++) {
            int i = tid + j * 256;
            int kr = i >> 4, s = i & 15;
            uint32_t dd = d + 2 * ASZ + (uint32_t)(kr * RB + s * 16);
            size_t so = (size_t)(k0 + kr) * ldb + s * 8;
            cpa16(dd, Bbh + so);
            cpa16(dd + BSZ, Bbl + so);
        }
        cpcommit();
    };

    float acc[4][4][4];
#pragma unroll
    for (int i = 0; i < 4; i++)
#pragma unroll
        for (int j = 0; j < 4; j++)
#pragma unroll
            for (int q = 0; q < 4; q++) acc[i][j][q] = 0.f;

    const int lr = lane & 15;
    const int ac8 = (lane >> 4) << 3;

    auto domma = [&](int buf) {
        const uint32_t ah = sb + buf * STAGE;
        const uint32_t al = ah + ASZ;
        const uint32_t bh = al + ASZ;
        const uint32_t bl = bh + BSZ;
#pragma unroll
        for (int kk = 0; kk < 2; kk++) {
            uint32_t bhf[2][4], blf[2][4];
#pragma unroll
            for (int nb = 0; nb < 2; nb++) {
                uint32_t boff = (uint32_t)(kk * 16 + lr) * RB +
                                (uint32_t)(wn * 32 + nb * 16 + ac8) * 2;
                ldsm4t(bhf[nb], bh + boff);
                ldsm4t(blf[nb], bl + boff);
            }
#pragma unroll
            for (int mi = 0; mi < 4; mi++) {
                uint32_t aoff = (uint32_t)(wm * 64 + mi * 16 + lr) * RA +
                                (uint32_t)(kk * 16 + ac8) * 2;
                uint32_t ahf[4], alf[4];
                ldsm4(ahf, ah + aoff);
#pragma unroll
                for (int nb = 0; nb < 2; nb++) {
                    mma_bf16(acc[mi][2 * nb], ahf, &bhf[nb][0]);
                    mma_bf16(acc[mi][2 * nb + 1], ahf, &bhf[nb][2]);
                    mma_bf16(acc[mi][2 * nb], ahf, &blf[nb][0]);
                    mma_bf16(acc[mi][2 * nb + 1], ahf, &blf[nb][2]);
                }
                ldsm4(alf, al + aoff);
#pragma unroll
                for (int nb = 0; nb < 2; nb++) {
                    mma_bf16(acc[mi][2 * nb], alf, &bhf[nb][0]);
                    mma_bf16(acc[mi][2 * nb + 1], alf, &bhf[nb][2]);
                }
            }
        }
    };

    const int T = K >> 5;
    issue(0, 0);
    issue(32, 1);
    cpwait<1>();
    __syncthreads();
#pragma unroll 1
    for (int t = 0; t < T; t++) {
        domma(t & 1);
        __syncthreads();
        if (t + 2 < T) issue((t + 2) * 32, t & 1);
        if (t + 1 < T) {
            if (t + 2 < T) cpwait<1>();
            else cpwait<0>();
            __syncthreads();
        }
    }

    // epilogue
    const int g = lane >> 2, q = lane & 3;
    const size_t c0 = (size_t)by * 128 * ldb + (size_t)bx * 128;
#pragma unroll
    for (int mi = 0; mi < 4; mi++)
#pragma unroll
        for (int nj = 0; nj < 4; nj++) {
            int col = wn * 32 + nj * 8 + q * 2;
            float bv0 = BIAS ? bias[bx * 128 + col] : 0.f;
            float bv1 = BIAS ? bias[bx * 128 + col + 1] : 0.f;
#pragma unroll
            for (int rr = 0; rr < 2; rr++) {
                int row = wm * 64 + mi * 16 + g + rr * 8;
                float v0 = acc[mi][nj][rr * 2] + bv0;
                float v1 = acc[mi][nj][rr * 2 + 1] + bv1;
                if (RES) {
                    const float* rp = Res + c0 + (size_t)row * ldb + col;
                    v0 += rp[0];
                    v1 += rp[1];
                }
                if (GELU) {
                    float i0 = 0.7978845608028654f * (v0 + 0.044715f * v0 * v0 * v0);
                    v0 = 0.5f * v0 * (1.f + tanhf(i0));
                    float i1 = 0.7978845608028654f * (v1 + 0.044715f * v1 * v1 * v1);
                    v1 = 0.5f * v1 * (1.f + tanhf(i1));
                }
                if (OUTPAIR) {
                    uint32_t hw, lw;
                    split2(v0, v1, hw, lw);
                    *(uint32_t*)(Ch + c0 + (size_t)row * ldb + col) = hw;
                    *(uint32_t*)(Cl + c0 + (size_t)row * ldb + col) = lw;
                } else {
                    *(float2*)(Cf + c0 + (size_t)row * ldb + col) = make_float2(v0, v1);
                }
            }
        }
}

template <int BIAS, int RES, int GELU, int OUTPAIR>
__global__ __launch_bounds__(256, 2) void pair_gemm(
    const ushortx* Ah, const ushortx* Al, const ushortx* Bh, const ushortx* Bl,
    const float* bias, const float* Res, float* Cf, ushortx* Ch, ushortx* Cl,
    int K, int lda, int ldb) {
    gemm_core<BIAS, RES, GELU, OUTPAIR>(Ah, Al, Bh, Bl, bias, Res, Cf, Ch, Cl, K, lda, ldb,
                                        blockIdx.x, blockIdx.y);
}

// split-K partial GEMM: z selects K chunk, writes raw fp32 partial
template <int SPLIT>
__global__ __launch_bounds__(256, 2) void pk_gemm(
    const ushortx* Ah, const ushortx* Al, const ushortx* Bh, const ushortx* Bl,
    float* P, int Ktot, int lda, int ldb) {
    const int z = blockIdx.z;
    const int Ks = Ktot / SPLIT;
    gemm_core<0, 0, 0, 0>(Ah + (size_t)z * Ks, Al + (size_t)z * Ks,
                          Bh + (size_t)z * Ks * ldb, Bl + (size_t)z * Ks * ldb,
                          nullptr, nullptr, P + (size_t)z * NT * DD, nullptr, nullptr,
                          Ks, lda, ldb, blockIdx.x, blockIdx.y);
}

// fused QKV
__global__ __launch_bounds__(256, 2) void qkv_gemm(
    const ushortx* xqh, const ushortx* xql, const ushortx* kvh, const ushortx* kvl,
    const ushortx* wqh, const ushortx* wql, const ushortx* wkh, const ushortx* wkl,
    const ushortx* wvh, const ushortx* wvl,
    const float* bq, const float* bk, const float* bv,
    ushortx* qh, ushortx* ql, ushortx* kh, ushortx* kl, ushortx* vh, ushortx* vl) {
    int z = blockIdx.z;
    const ushortx *Ah, *Al, *Bh, *Bl;
    const float* bias;
    ushortx *Ch, *Cl;
    int K, lda;
    if (z == 0) {
        Ah = xqh; Al = xql; Bh = wqh; Bl = wql; bias = bq; Ch = qh; Cl = ql;
        K = DD; lda = DD;
    } else if (z == 1) {
        Ah = kvh; Al = kvl; Bh = wkh; Bl = wkl; bias = bk; Ch = kh; Cl = kl;
        K = CC; lda = CC;
    } else {
        Ah = kvh; Al = kvl; Bh = wvh; Bl = wvl; bias = bv; Ch = vh; Cl = vl;
        K = CC; lda = CC;
    }
    gemm_core<1, 0, 0, 1>(Ah, Al, Bh, Bl, bias, nullptr, nullptr, Ch, Cl, K, lda, DD,
                          blockIdx.x, blockIdx.y);
}

// ---------------- flash attention (bf16-pair in/out) --------------------------
__global__ __launch_bounds__(256, 2) void flash_kernel(
    const ushortx* __restrict__ Qh, const ushortx* __restrict__ Ql,
    const ushortx* __restrict__ Kh, const ushortx* __restrict__ Kl,
    const ushortx* __restrict__ Vh, const ushortx* __restrict__ Vl,
    ushortx* __restrict__ Oh, ushortx* __restrict__ Ol) {
    constexpr int R = 144;
    constexpr int QHo = 0, QLo = 18432, KHS = 36864, KLS = 46080, VHS = 55296, VLS = 64512;

    extern __shared__ char sm[];
    const int tid = threadIdx.x, lane = tid & 31, wid = tid >> 5;
    const int h = blockIdx.y, qb = blockIdx.x;
    const uint32_t sb = smem_addr_u32(sm);

    const ushortx* Qgh = Qh + (size_t)qb * 128 * DD + h * HD;
    const ushortx* Qgl = Ql + (size_t)qb * 128 * DD + h * HD;
    const ushortx* Kgh = Kh + h * HD;
    const ushortx* Kgl = Kl + h * HD;
    const ushortx* Vgh = Vh + h * HD;
    const ushortx* Vgl = Vl + h * HD;

#pragma unroll
    for (int j = 0; j < 4; j++) {
        int i = tid + j * 256;
        int r = i >> 3, s = i & 7;
        uint32_t dd = sb + (uint32_t)(r * R + s * 16);
        size_t so = (size_t)r * DD + s * 8;
        cpa16(dd + QHo, Qgh + so);
        cpa16(dd + QLo, Qgl + so);
    }
    auto issueKV = [&](int kb) {
#pragma unroll
        for (int j = 0; j < 2; j++) {
            int i = tid + j * 256;
            int r = i >> 3, s = i & 7;
            uint32_t dd = sb + (uint32_t)(r * R + s * 16);
            size_t so = (size_t)(kb * 64 + r) * DD + s * 8;
            cpa16(dd + KHS, Kgh + so);
            cpa16(dd + KLS, Kgl + so);
            cpa16(dd + VHS, Vgh + so);
            cpa16(dd + VLS, Vgl + so);
        }
        cpcommit();
    };
    issueKV(0);

    float o[8][4];
#pragma unroll
    for (int i = 0; i < 8; i++)
#pragma unroll
        for (int j = 0; j < 4; j++) o[i][j] = 0.f;
    float m0 = -INFINITY, m1 = -INFINITY, l0 = 0.f, l1 = 0.f;

    const int lr = lane & 15;
    const int ac8 = (lane >> 4) << 3;
    const int bn = (lane & 7) + ((lane >> 4) << 3);
    const int bc8 = ((lane >> 3) & 1) << 3;

    for (int kb = 0; kb < MT / 64; kb++) {
        cpwait<0>();
        __syncthreads();

        float s[8][4];
#pragma unroll
        for (int i = 0; i < 8; i++)
#pragma unroll
            for (int j = 0; j < 4; j++) s[i][j] = 0.f;
#pragma unroll
        for (int kf = 0; kf < 4; kf++) {
            uint32_t aoff = (uint32_t)(wid * 16 + lr) * R + (uint32_t)(kf * 16 + ac8) * 2;
            uint32_t qhr[4], qlr[4], khr[4][4], klr[4][4];
            ldsm4(qhr, sb + QHo + aoff);
#pragma unroll
            for (int nb = 0; nb < 4; nb++) {
                uint32_t boff = (uint32_t)(nb * 16 + bn) * R + (uint32_t)(kf * 16 + bc8) * 2;
                ldsm4(khr[nb], sb + KHS + boff);
            }
#pragma unroll
            for (int nb = 0; nb < 4; nb++) {
                mma_bf16(s[2 * nb], qhr, &khr[nb][0]);
                mma_bf16(s[2 * nb + 1], qhr, &khr[nb][2]);
            }
            ldsm4(qlr, sb + QLo + aoff);
#pragma unroll
            for (int nb = 0; nb < 4; nb++) {
                mma_bf16(s[2 * nb], qlr, &khr[nb][0]);
                mma_bf16(s[2 * nb + 1], qlr, &khr[nb][2]);
            }
#pragma unroll
            for (int nb = 0; nb < 4; nb++) {
                uint32_t boff = (uint32_t)(nb * 16 + bn) * R + (uint32_t)(kf * 16 + bc8) * 2;
                ldsm4(klr[nb], sb + KLS + boff);
            }
#pragma unroll
            for (int nb = 0; nb < 4; nb++) {
                mma_bf16(s[2 * nb], qhr, &klr[nb][0]);
                mma_bf16(s[2 * nb + 1], qhr, &klr[nb][2]);
            }
        }

        float mx0 = -INFINITY, mx1 = -INFINITY;
#pragma unroll
        for (int j = 0; j < 8; j++) {
            mx0 = fmaxf(mx0, fmaxf(s[j][0], s[j][1]));
            mx1 = fmaxf(mx1, fmaxf(s[j][2], s[j][3]));
        }
        mx0 = fmaxf(mx0, __shfl_xor_sync(0xffffffffu, mx0, 1));
        mx0 = fmaxf(mx0, __shfl_xor_sync(0xffffffffu, mx0, 2));
        mx1 = fmaxf(mx1, __shfl_xor_sync(0xffffffffu, mx1, 1));
        mx1 = fmaxf(mx1, __shfl_xor_sync(0xffffffffu, mx1, 2));
        float m0n = fmaxf(m0, mx0), m1n = fmaxf(m1, mx1);
        float sc0 = __expf((m0 - m0n) * 0.125f);
        float sc1 = __expf((m1 - m1n) * 0.125f);
        m0 = m0n;
        m1 = m1n;
        float su0 = 0.f, su1 = 0.f;
#pragma unroll
        for (int j = 0; j < 8; j++) {
            s[j][0] = __expf((s[j][0] - m0) * 0.125f);
            s[j][1] = __expf((s[j][1] - m0) * 0.125f);
            s[j][2] = __expf((s[j][2] - m1) * 0.125f);
            s[j][3] = __expf((s[j][3] - m1) * 0.125f);
            su0 += s[j][0] + s[j][1];
            su1 += s[j][2] + s[j][3];
        }
        su0 += __shfl_xor_sync(0xffffffffu, su0, 1);
        su0 += __shfl_xor_sync(0xffffffffu, su0, 2);
        su1 += __shfl_xor_sync(0xffffffffu, su1, 1);
        su1 += __shfl_xor_sync(0xffffffffu, su1, 2);
        l0 = l0 * sc0 + su0;
        l1 = l1 * sc1 + su1;
#pragma unroll
        for (int j = 0; j < 8; j++) {
            o[j][0] *= sc0;
            o[j][1] *= sc0;
            o[j][2] *= sc1;
            o[j][3] *= sc1;
        }

#pragma unroll
        for (int kf = 0; kf < 4; kf++) {
            uint32_t ph[4], pl[4];
            split2(s[2 * kf][0], s[2 * kf][1], ph[0], pl[0]);
            split2(s[2 * kf][2], s[2 * kf][3], ph[1], pl[1]);
            split2(s[2 * kf + 1][0], s[2 * kf + 1][1], ph[2], pl[2]);
            split2(s[2 * kf + 1][2], s[2 * kf + 1][3], ph[3], pl[3]);
            uint32_t vhr[4][4], vlr[4][4];
#pragma unroll
            for (int nb = 0; nb < 4; nb++) {
                uint32_t boff = (uint32_t)(kf * 16 + lr) * R + (uint32_t)(nb * 16 + ac8) * 2;
                ldsm4t(vhr[nb], sb + VHS + boff);
            }
#pragma unroll
            for (int nb = 0; nb < 4; nb++) {
                mma_bf16(o[2 * nb], ph, &vhr[nb][0]);
                mma_bf16(o[2 * nb + 1], ph, &vhr[nb][2]);
                mma_bf16(o[2 * nb], pl, &vhr[nb][0]);
                mma_bf16(o[2 * nb + 1], pl, &vhr[nb][2]);
            }
#pragma unroll
            for (int nb = 0; nb < 4; nb++) {
                uint32_t boff = (uint32_t)(kf * 16 + lr) * R + (uint32_t)(nb * 16 + ac8) * 2;
                ldsm4t(vlr[nb], sb + VLS + boff);
            }
#pragma unroll
            for (int nb = 0; nb < 4; nb++) {
                mma_bf16(o[2 * nb], ph, &vlr[nb][0]);
                mma_bf16(o[2 * nb + 1], ph, &vlr[nb][2]);
            }
        }
        __syncthreads();
        if (kb + 1 < MT / 64) issueKV(kb + 1);
    }

    float i0 = 1.f / l0, i1 = 1.f / l1;
    const int g = lane >> 2, q = lane & 3;
    size_t base = (size_t)(qb * 128 + wid * 16) * DD + h * HD;
#pragma unroll
    for (int nj = 0; nj < 8; nj++) {
        int col = nj * 8 + q * 2;
        uint32_t hw, lw;
        split2(o[nj][0] * i0, o[nj][1] * i0, hw, lw);
        *(uint32_t*)(Oh + base + (size_t)g * DD + col) = hw;
        *(uint32_t*)(Ol + base + (size_t)g * DD + col) = lw;
        split2(o[nj][2] * i1, o[nj][3] * i1, hw, lw);
        *(uint32_t*)(Oh + base + (size_t)(g + 8) * DD + col) = hw;
        *(uint32_t*)(Ol + base + (size_t)(g + 8) * DD + col) = lw;
    }
}

// ---------------- launch -----------------------------------------------------
extern "C" void kernel_launch(void* const* d_in, const int* in_sizes, int n_in,
                              void* d_out, int out_size) {
    const float* x     = (const float*)d_in[0];
    const float* ctx   = (const float*)d_in[1];
    const float* wq    = (const float*)d_in[2];
    const float* bq    = (const float*)d_in[3];
    const float* wk    = (const float*)d_in[4];
    const float* bk    = (const float*)d_in[5];
    const float* wv    = (const float*)d_in[6];
    const float* bv    = (const float*)d_in[7];
    const float* wo    = (const float*)d_in[8];
    const float* bo    = (const float*)d_in[9];
    const float* w1    = (const float*)d_in[10];
    const float* b1    = (const float*)d_in[11];
    const float* w2    = (const float*)d_in[12];
    const float* b2    = (const float*)d_in[13];
    const float* qn_w  = (const float*)d_in[14];
    const float* qn_b  = (const float*)d_in[15];
    const float* kvn_w = (const float*)d_in[16];
    const float* kvn_b = (const float*)d_in[17];
    const float* pn_w  = (const float*)d_in[18];
    const float* pn_b  = (const float*)d_in[19];
    float* out = (float*)d_out;

#define GETP(name) \
    ushortx* name; cudaGetSymbolAddress((void**)&name, g_##name)
    GETP(xqh); GETP(xql); GETP(kvh); GETP(kvl);
    GETP(qh); GETP(ql); GETP(kh); GETP(kl); GETP(vh); GETP(vl);
    GETP(oh); GETP(ol); GETP(hlnh); GETP(hlnl); GETP(h1h); GETP(h1l);
    GETP(wqh); GETP(wql); GETP(wkh); GETP(wkl); GETP(wvh); GETP(wvl);
    GETP(woh); GETP(wol); GETP(w1h); GETP(w1l); GETP(w2h); GETP(w2l);
#undef GETP
    float *x1, *part;
    cudaGetSymbolAddress((void**)&x1, g_x1);
    cudaGetSymbolAddress((void**)&part, g_part);

    const int GSM = 2 * 37888;
    const int FSM = 73728;
    cudaFuncSetAttribute((const void*)qkv_gemm,
                         cudaFuncAttributeMaxDynamicSharedMemorySize, GSM);
    cudaFuncSetAttribute((const void*)pair_gemm<1, 0, 1, 1>,
                         cudaFuncAttributeMaxDynamicSharedMemorySize, GSM);
    cudaFuncSetAttribute((const void*)pk_gemm<2>,
                         cudaFuncAttributeMaxDynamicSharedMemorySize, GSM);
    cudaFuncSetAttribute((const void*)pk_gemm<4>,
                         cudaFuncAttributeMaxDynamicSharedMemorySize, GSM);
    cudaFuncSetAttribute((const void*)flash_kernel,
                         cudaFuncAttributeMaxDynamicSharedMemorySize, FSM);

    // 0. convert all weights (one launch)
    convert_all<<<dim3(4096, 6), 256>>>(wq, wk, wv, wo, w1, w2,
                                        wqh, wql, wkh, wkl, wvh, wvl,
                                        woh, wol, w1h, w1l, w2h, w2l);

    // 1. pre-norms -> bf16 pairs
    ln_pair_kernel<DD><<<NT, 256>>>(x, qn_w, qn_b, xqh, xql);
    ln_pair_kernel<CC><<<MT, 256>>>(ctx, kvn_w, kvn_b, kvh, kvl);

    // 2. fused Q/K/V projections
    qkv_gemm<<<dim3(DD / 128, NT / 128, 3), 256, GSM>>>(
        xqh, xql, kvh, kvl, wqh, wql, wkh, wkl, wvh, wvl, bq, bk, bv,
        qh, ql, kh, kl, vh, vl);

    // 3. fused attention
    flash_kernel<<<dim3(NT / 128, NH), 256, FSM>>>(qh, ql, kh, kl, vh, vl, oh, ol);

    // 4. x1 = o @ wo + bo + x   (split-K=2)
    pk_gemm<2><<<dim3(DD / 128, NT / 128, 2), 256, GSM>>>(
        oh, ol, woh, wol, part, DD, DD, DD);
    combine_kernel<2><<<NT * DD / 4 / 256, 256>>>(part, bo, x, x1);

    // 5. MLP
    ln_pair_kernel<DD><<<NT, 256>>>(x1, pn_w, pn_b, hlnh, hlnl);
    pair_gemm<1, 0, 1, 1><<<dim3(FF / 128, NT / 128), 256, GSM>>>(
        hlnh, hlnl, w1h, w1l, b1, nullptr, nullptr, h1h, h1l, DD, DD, FF);
    pk_gemm<4><<<dim3(DD / 128, NT / 128, 4), 256, GSM>>>(
        h1h, h1l, w2h, w2l, part, FF, FF, DD);
    combine_kernel<4><<<NT * DD / 4 / 256, 256>>>(part, b2, x1, out);
}

// round 7
// speedup vs baseline: 1.4288x; 1.4288x over previous
#include <cuda_runtime.h>
#include <cuda_bf16.h>
#include <math.h>
#include <stdint.h>

#define NT 2048
#define DD 1024
#define CC 768
#define NH 16
#define HD 64
#define MT 2048
#define FF 4096

typedef unsigned short ushortx;

// ---------------- scratch (bf16 pairs stored as ushort) ----------------------
__device__ ushortx g_xqh[NT * DD], g_xql[NT * DD];
__device__ ushortx g_kvh[MT * CC], g_kvl[MT * CC];
__device__ ushortx g_qh[NT * DD], g_ql[NT * DD];
__device__ ushortx g_kh[MT * DD], g_kl[MT * DD];
__device__ ushortx g_vh[MT * DD], g_vl[MT * DD];
__device__ ushortx g_oh[NT * DD], g_ol[NT * DD];
__device__ float   g_x1[NT * DD];
__device__ ushortx g_hlnh[NT * DD], g_hlnl[NT * DD];
__device__ ushortx g_h1h[(size_t)NT * FF], g_h1l[(size_t)NT * FF];
__device__ ushortx g_wqh[DD * DD], g_wql[DD * DD];
__device__ ushortx g_wkh[CC * DD], g_wkl[CC * DD];
__device__ ushortx g_wvh[CC * DD], g_wvl[CC * DD];
__device__ ushortx g_woh[DD * DD], g_wol[DD * DD];
__device__ ushortx g_w1h[(size_t)DD * FF], g_w1l[(size_t)DD * FF];
__device__ ushortx g_w2h[(size_t)FF * DD], g_w2l[(size_t)FF * DD];

// ---------------- helpers ----------------------------------------------------
__device__ __forceinline__ uint32_t smem_addr_u32(const void* p) {
    uint32_t a;
    asm("{ .reg .u64 t; cvta.to.shared.u64 t, %1; cvt.u32.u64 %0, t; }" : "=r"(a) : "l"(p));
    return a;
}
__device__ __forceinline__ void ldsm4(uint32_t* r, uint32_t addr) {
    asm volatile("ldmatrix.sync.aligned.m8n8.x4.shared.b16 {%0,%1,%2,%3}, [%4];"
                 : "=r"(r[0]), "=r"(r[1]), "=r"(r[2]), "=r"(r[3]) : "r"(addr));
}
__device__ __forceinline__ void ldsm4t(uint32_t* r, uint32_t addr) {
    asm volatile("ldmatrix.sync.aligned.m8n8.x4.trans.shared.b16 {%0,%1,%2,%3}, [%4];"
                 : "=r"(r[0]), "=r"(r[1]), "=r"(r[2]), "=r"(r[3]) : "r"(addr));
}
__device__ __forceinline__ void mma_bf16(float* d, const uint32_t* a, const uint32_t* b) {
    asm volatile(
        "mma.sync.aligned.m16n8k16.row.col.f32.bf16.bf16.f32 "
        "{%0,%1,%2,%3}, {%4,%5,%6,%7}, {%8,%9}, {%0,%1,%2,%3};"
        : "+f"(d[0]), "+f"(d[1]), "+f"(d[2]), "+f"(d[3])
        : "r"(a[0]), "r"(a[1]), "r"(a[2]), "r"(a[3]), "r"(b[0]), "r"(b[1]));
}
__device__ __forceinline__ void split2(float x, float y, uint32_t& h, uint32_t& l) {
    __nv_bfloat16 xh = __float2bfloat16(x), yh = __float2bfloat16(y);
    float xr = x - __bfloat162float(xh);
    float yr = y - __bfloat162float(yh);
    __nv_bfloat16 xl = __float2bfloat16(xr), yl = __float2bfloat16(yr);
    h = (uint32_t)__bfloat16_as_ushort(xh) | ((uint32_t)__bfloat16_as_ushort(yh) << 16);
    l = (uint32_t)__bfloat16_as_ushort(xl) | ((uint32_t)__bfloat16_as_ushort(yl) << 16);
}
__device__ __forceinline__ void cpa16(uint32_t d, const void* g) {
    asm volatile("cp.async.cg.shared.global [%0], [%1], 16;" :: "r"(d), "l"(g));
}
__device__ __forceinline__ void cpcommit() { asm volatile("cp.async.commit_group;" ::: "memory"); }
template <int N>
__device__ __forceinline__ void cpwait() {
    asm volatile("cp.async.wait_group %0;" :: "n"(N) : "memory");
}

// ---------------- convert fp32 -> bf16 hi/lo ---------------------------------
__global__ __launch_bounds__(256) void convert_kernel(
    const float* __restrict__ s, ushortx* __restrict__ h, ushortx* __restrict__ l, int n4) {
    int i = blockIdx.x * 256 + threadIdx.x;
    if (i >= n4) return;
    float4 f = ((const float4*)s)[i];
    uint32_t h0, l0, h1, l1;
    split2(f.x, f.y, h0, l0);
    split2(f.z, f.w, h1, l1);
    ((uint2*)h)[i] = make_uint2(h0, h1);
    ((uint2*)l)[i] = make_uint2(l0, l1);
}

// ---------------- layernorm -> bf16 pair -------------------------------------
__device__ __forceinline__ float block_reduce_sum(float v) {
    __shared__ float sh[8];
    int tid = threadIdx.x;
#pragma unroll
    for (int o = 16; o > 0; o >>= 1) v += __shfl_down_sync(0xffffffffu, v, o);
    if ((tid & 31) == 0) sh[tid >> 5] = v;
    __syncthreads();
    if (tid < 32) {
        v = (tid < 8) ? sh[tid] : 0.f;
#pragma unroll
        for (int o = 4; o > 0; o >>= 1) v += __shfl_down_sync(0xffffffffu, v, o);
        if (tid == 0) sh[0] = v;
    }
    __syncthreads();
    float r = sh[0];
    __syncthreads();
    return r;
}

template <int DIM>
__global__ __launch_bounds__(256) void ln_pair_kernel(
    const float* __restrict__ x, const float* __restrict__ w, const float* __restrict__ b,
    ushortx* __restrict__ oh, ushortx* __restrict__ ol) {
    const float* xr = x + (size_t)blockIdx.x * DIM;
    int tid = threadIdx.x;
    float4 f = make_float4(0.f, 0.f, 0.f, 0.f);
    if (tid < DIM / 4) f = ((const float4*)xr)[tid];
    float s = f.x + f.y + f.z + f.w;
    float mean = block_reduce_sum(s) * (1.f / DIM);
    float vv = 0.f;
    if (tid < DIM / 4) {
        float c0 = f.x - mean, c1 = f.y - mean, c2 = f.z - mean, c3 = f.w - mean;
        vv = c0 * c0 + c1 * c1 + c2 * c2 + c3 * c3;
    }
    float var = block_reduce_sum(vv) * (1.f / DIM);
    float inv = rsqrtf(var + 1e-12f);
    if (tid < DIM / 4) {
        float4 w4 = ((const float4*)w)[tid];
        float4 b4 = ((const float4*)b)[tid];
        float o0 = (f.x - mean) * inv * w4.x + b4.x;
        float o1 = (f.y - mean) * inv * w4.y + b4.y;
        float o2 = (f.z - mean) * inv * w4.z + b4.z;
        float o3 = (f.w - mean) * inv * w4.w + b4.w;
        uint32_t h0, l0, h1, l1;
        split2(o0, o1, h0, l0);
        split2(o2, o3, h1, l1);
        ((uint2*)(oh + (size_t)blockIdx.x * DIM))[tid] = make_uint2(h0, h1);
        ((uint2*)(ol + (size_t)blockIdx.x * DIM))[tid] = make_uint2(l0, l1);
    }
}

// ---------------- bf16-pair GEMM core (3-stage cp.async, 1 sync/tile) ---------
template <int BIAS, int RES, int GELU, int OUTPAIR>
__device__ __forceinline__ void gemm_core(
    const ushortx* __restrict__ Ah, const ushortx* __restrict__ Al,
    const ushortx* __restrict__ Bh, const ushortx* __restrict__ Bl,
    const float* __restrict__ bias, const float* __restrict__ Res,
    float* __restrict__ Cf, ushortx* __restrict__ Ch, ushortx* __restrict__ Cl,
    int K, int lda, int ldb, int bx, int by) {
    constexpr int RA = 80, RB = 272;
    constexpr int ASZ = 128 * RA;
    constexpr int BSZ = 32 * RB;
    constexpr int STAGE = 2 * ASZ + 2 * BSZ;  // 37888

    extern __shared__ char sm[];
    const int tid = threadIdx.x, lane = tid & 31, wid = tid >> 5;
    const int wm = wid & 1, wn = wid >> 1;
    const uint32_t sb = smem_addr_u32(sm);

    const ushortx* Abh = Ah + (size_t)by * 128 * lda;
    const ushortx* Abl = Al + (size_t)by * 128 * lda;
    const ushortx* Bbh = Bh + (size_t)bx * 128;
    const ushortx* Bbl = Bl + (size_t)bx * 128;

    auto issue = [&](int k0, int buf) {
        uint32_t d = sb + buf * STAGE;
#pragma unroll
        for (int j = 0; j < 2; j++) {
            int i = tid + j * 256;
            int r = i >> 2, s = i & 3;
            uint32_t dd = d + (uint32_t)(r * RA + s * 16);
            size_t so = (size_t)r * lda + k0 + s * 8;
            cpa16(dd, Abh + so);
            cpa16(dd + ASZ, Abl + so);
        }
#pragma unroll
        for (int j = 0; j < 2; j++) {
            int i = tid + j * 256;
            int kr = i >> 4, s = i & 15;
            uint32_t dd = d + 2 * ASZ + (uint32_t)(kr * RB + s * 16);
            size_t so = (size_t)(k0 + kr) * ldb + s * 8;
            cpa16(dd, Bbh + so);
            cpa16(dd + BSZ, Bbl + so);
        }
        cpcommit();
    };

    float acc[4][4][4];
#pragma unroll
    for (int i = 0; i < 4; i++)
#pragma unroll
        for (int j = 0; j < 4; j++)
#pragma unroll
            for (int q = 0; q < 4; q++) acc[i][j][q] = 0.f;

    const int lr = lane & 15;
    const int ac8 = (lane >> 4) << 3;

    auto domma = [&](int buf) {
        const uint32_t ah = sb + buf * STAGE;
        const uint32_t al = ah + ASZ;
        const uint32_t bh = al + ASZ;
        const uint32_t bl = bh + BSZ;
#pragma unroll
        for (int kk = 0; kk < 2; kk++) {
            uint32_t bhf[2][4], blf[2][4];
#pragma unroll
            for (int nb = 0; nb < 2; nb++) {
                uint32_t boff = (uint32_t)(kk * 16 + lr) * RB +
                                (uint32_t)(wn * 32 + nb * 16 + ac8) * 2;
                ldsm4t(bhf[nb], bh + boff);
                ldsm4t(blf[nb], bl + boff);
            }
#pragma unroll
            for (int mi = 0; mi < 4; mi++) {
                uint32_t aoff = (uint32_t)(wm * 64 + mi * 16 + lr) * RA +
                                (uint32_t)(kk * 16 + ac8) * 2;
                uint32_t ahf[4], alf[4];
                ldsm4(ahf, ah + aoff);
#pragma unroll
                for (int nb = 0; nb < 2; nb++) {
                    mma_bf16(acc[mi][2 * nb], ahf, &bhf[nb][0]);
                    mma_bf16(acc[mi][2 * nb + 1], ahf, &bhf[nb][2]);
                    mma_bf16(acc[mi][2 * nb], ahf, &blf[nb][0]);
                    mma_bf16(acc[mi][2 * nb + 1], ahf, &blf[nb][2]);
                }
                ldsm4(alf, al + aoff);
#pragma unroll
                for (int nb = 0; nb < 2; nb++) {
                    mma_bf16(acc[mi][2 * nb], alf, &bhf[nb][0]);
                    mma_bf16(acc[mi][2 * nb + 1], alf, &bhf[nb][2]);
                }
            }
        }
    };

    const int T = K >> 5;
    issue(0, 0);
    issue(32, 1);
#pragma unroll 1
    for (int t = 0; t < T; t++) {
        if (t < T - 1) cpwait<1>();
        else cpwait<0>();
        __syncthreads();
        if (t + 2 < T) {
            int b2 = t + 2;
            issue(b2 * 32, b2 - (b2 / 3) * 3);
        }
        domma(t - (t / 3) * 3);
    }

    // epilogue
    const int g = lane >> 2, q = lane & 3;
    const size_t c0 = (size_t)by * 128 * ldb + (size_t)bx * 128;
#pragma unroll
    for (int mi = 0; mi < 4; mi++)
#pragma unroll
        for (int nj = 0; nj < 4; nj++) {
            int col = wn * 32 + nj * 8 + q * 2;
            float bv0 = BIAS ? bias[bx * 128 + col] : 0.f;
            float bv1 = BIAS ? bias[bx * 128 + col + 1] : 0.f;
#pragma unroll
            for (int rr = 0; rr < 2; rr++) {
                int row = wm * 64 + mi * 16 + g + rr * 8;
                float v0 = acc[mi][nj][rr * 2] + bv0;
                float v1 = acc[mi][nj][rr * 2 + 1] + bv1;
                if (RES) {
                    const float* rp = Res + c0 + (size_t)row * ldb + col;
                    v0 += rp[0];
                    v1 += rp[1];
                }
                if (GELU) {
                    float i0 = 0.7978845608028654f * (v0 + 0.044715f * v0 * v0 * v0);
                    v0 = 0.5f * v0 * (1.f + tanhf(i0));
                    float i1 = 0.7978845608028654f * (v1 + 0.044715f * v1 * v1 * v1);
                    v1 = 0.5f * v1 * (1.f + tanhf(i1));
                }
                if (OUTPAIR) {
                    uint32_t hw, lw;
                    split2(v0, v1, hw, lw);
                    *(uint32_t*)(Ch + c0 + (size_t)row * ldb + col) = hw;
                    *(uint32_t*)(Cl + c0 + (size_t)row * ldb + col) = lw;
                } else {
                    *(float2*)(Cf + c0 + (size_t)row * ldb + col) = make_float2(v0, v1);
                }
            }
        }
}

template <int BIAS, int RES, int GELU, int OUTPAIR>
__global__ __launch_bounds__(256, 2) void pair_gemm(
    const ushortx* Ah, const ushortx* Al, const ushortx* Bh, const ushortx* Bl,
    const float* bias, const float* Res, float* Cf, ushortx* Ch, ushortx* Cl,
    int K, int lda, int ldb) {
    gemm_core<BIAS, RES, GELU, OUTPAIR>(Ah, Al, Bh, Bl, bias, Res, Cf, Ch, Cl, K, lda, ldb,
                                        blockIdx.x, blockIdx.y);
}

// fused QKV
__global__ __launch_bounds__(256, 2) void qkv_gemm(
    const ushortx* xqh, const ushortx* xql, const ushortx* kvh, const ushortx* kvl,
    const ushortx* wqh, const ushortx* wql, const ushortx* wkh, const ushortx* wkl,
    const ushortx* wvh, const ushortx* wvl,
    const float* bq, const float* bk, const float* bv,
    ushortx* qh, ushortx* ql, ushortx* kh, ushortx* kl, ushortx* vh, ushortx* vl) {
    int z = blockIdx.z;
    const ushortx *Ah, *Al, *Bh, *Bl;
    const float* bias;
    ushortx *Ch, *Cl;
    int K, lda;
    if (z == 0) {
        Ah = xqh; Al = xql; Bh = wqh; Bl = wql; bias = bq; Ch = qh; Cl = ql;
        K = DD; lda = DD;
    } else if (z == 1) {
        Ah = kvh; Al = kvl; Bh = wkh; Bl = wkl; bias = bk; Ch = kh; Cl = kl;
        K = CC; lda = CC;
    } else {
        Ah = kvh; Al = kvl; Bh = wvh; Bl = wvl; bias = bv; Ch = vh; Cl = vl;
        K = CC; lda = CC;
    }
    gemm_core<1, 0, 0, 1>(Ah, Al, Bh, Bl, bias, nullptr, nullptr, Ch, Cl, K, lda, DD,
                          blockIdx.x, blockIdx.y);
}

// ---------------- flash attention (double-buffered KV) ------------------------
__global__ __launch_bounds__(256, 2) void flash_kernel(
    const ushortx* __restrict__ Qh, const ushortx* __restrict__ Ql,
    const ushortx* __restrict__ Kh, const ushortx* __restrict__ Kl,
    const ushortx* __restrict__ Vh, const ushortx* __restrict__ Vl,
    ushortx* __restrict__ Oh, ushortx* __restrict__ Ol) {
    constexpr int R = 144;
    constexpr int QHo = 0, QLo = 18432;
    constexpr int KVB0 = 36864, KVSZ = 36864;   // per-stage: KH,KL,VH,VL each 9216
    constexpr int NKB = MT / 64;

    extern __shared__ char sm[];
    const int tid = threadIdx.x, lane = tid & 31, wid = tid >> 5;
    const int h = blockIdx.y, qb = blockIdx.x;
    const uint32_t sb = smem_addr_u32(sm);

    const ushortx* Qgh = Qh + (size_t)qb * 128 * DD + h * HD;
    const ushortx* Qgl = Ql + (size_t)qb * 128 * DD + h * HD;
    const ushortx* Kgh = Kh + h * HD;
    const ushortx* Kgl = Kl + h * HD;
    const ushortx* Vgh = Vh + h * HD;
    const ushortx* Vgl = Vl + h * HD;

    // Q loads join the first KV commit group
#pragma unroll
    for (int j = 0; j < 4; j++) {
        int i = tid + j * 256;
        int r = i >> 3, s = i & 7;
        uint32_t dd = sb + (uint32_t)(r * R + s * 16);
        size_t so = (size_t)r * DD + s * 8;
        cpa16(dd + QHo, Qgh + so);
        cpa16(dd + QLo, Qgl + so);
    }
    auto issueKV = [&](int kb, int buf) {
        uint32_t base = sb + KVB0 + (uint32_t)buf * KVSZ;
#pragma unroll
        for (int j = 0; j < 2; j++) {
            int i = tid + j * 256;
            int r = i >> 3, s = i & 7;
            uint32_t dd = base + (uint32_t)(r * R + s * 16);
            size_t so = (size_t)(kb * 64 + r) * DD + s * 8;
            cpa16(dd + 0, Kgh + so);
            cpa16(dd + 9216, Kgl + so);
            cpa16(dd + 18432, Vgh + so);
            cpa16(dd + 27648, Vgl + so);
        }
        cpcommit();
    };
    issueKV(0, 0);
    issueKV(1, 1);

    float o[8][4];
#pragma unroll
    for (int i = 0; i < 8; i++)
#pragma unroll
        for (int j = 0; j < 4; j++) o[i][j] = 0.f;
    float m0 = -INFINITY, m1 = -INFINITY, l0 = 0.f, l1 = 0.f;

    const int lr = lane & 15;
    const int ac8 = (lane >> 4) << 3;
    const int bn = (lane & 7) + ((lane >> 4) << 3);
    const int bc8 = ((lane >> 3) & 1) << 3;

    for (int kb = 0; kb < NKB; kb++) {
        if (kb < NKB - 1) cpwait<1>();
        else cpwait<0>();
        __syncthreads();
        const uint32_t KVB = sb + KVB0 + (uint32_t)(kb & 1) * KVSZ;

        float s[8][4];
#pragma unroll
        for (int i = 0; i < 8; i++)
#pragma unroll
            for (int j = 0; j < 4; j++) s[i][j] = 0.f;
#pragma unroll
        for (int kf = 0; kf < 4; kf++) {
            uint32_t aoff = (uint32_t)(wid * 16 + lr) * R + (uint32_t)(kf * 16 + ac8) * 2;
            uint32_t qhr[4], qlr[4], khr[4][4], klr[4][4];
            ldsm4(qhr, sb + QHo + aoff);
#pragma unroll
            for (int nb = 0; nb < 4; nb++) {
                uint32_t boff = (uint32_t)(nb * 16 + bn) * R + (uint32_t)(kf * 16 + bc8) * 2;
                ldsm4(khr[nb], KVB + 0 + boff);
            }
#pragma unroll
            for (int nb = 0; nb < 4; nb++) {
                mma_bf16(s[2 * nb], qhr, &khr[nb][0]);
                mma_bf16(s[2 * nb + 1], qhr, &khr[nb][2]);
            }
            ldsm4(qlr, sb + QLo + aoff);
#pragma unroll
            for (int nb = 0; nb < 4; nb++) {
                mma_bf16(s[2 * nb], qlr, &khr[nb][0]);
                mma_bf16(s[2 * nb + 1], qlr, &khr[nb][2]);
            }
#pragma unroll
            for (int nb = 0; nb < 4; nb++) {
                uint32_t boff = (uint32_t)(nb * 16 + bn) * R + (uint32_t)(kf * 16 + bc8) * 2;
                ldsm4(klr[nb], KVB + 9216 + boff);
            }
#pragma unroll
            for (int nb = 0; nb < 4; nb++) {
                mma_bf16(s[2 * nb], qhr, &klr[nb][0]);
                mma_bf16(s[2 * nb + 1], qhr, &klr[nb][2]);
            }
        }

        float mx0 = -INFINITY, mx1 = -INFINITY;
#pragma unroll
        for (int j = 0; j < 8; j++) {
            mx0 = fmaxf(mx0, fmaxf(s[j][0], s[j][1]));
            mx1 = fmaxf(mx1, fmaxf(s[j][2], s[j][3]));
        }
        mx0 = fmaxf(mx0, __shfl_xor_sync(0xffffffffu, mx0, 1));
        mx0 = fmaxf(mx0, __shfl_xor_sync(0xffffffffu, mx0, 2));
        mx1 = fmaxf(mx1, __shfl_xor_sync(0xffffffffu, mx1, 1));
        mx1 = fmaxf(mx1, __shfl_xor_sync(0xffffffffu, mx1, 2));
        float m0n = fmaxf(m0, mx0), m1n = fmaxf(m1, mx1);
        float sc0 = __expf((m0 - m0n) * 0.125f);
        float sc1 = __expf((m1 - m1n) * 0.125f);
        m0 = m0n;
        m1 = m1n;
        float su0 = 0.f, su1 = 0.f;
#pragma unroll
        for (int j = 0; j < 8; j++) {
            s[j][0] = __expf((s[j][0] - m0) * 0.125f);
            s[j][1] = __expf((s[j][1] - m0) * 0.125f);
            s[j][2] = __expf((s[j][2] - m1) * 0.125f);
            s[j][3] = __expf((s[j][3] - m1) * 0.125f);
            su0 += s[j][0] + s[j][1];
            su1 += s[j][2] + s[j][3];
        }
        su0 += __shfl_xor_sync(0xffffffffu, su0, 1);
        su0 += __shfl_xor_sync(0xffffffffu, su0, 2);
        su1 += __shfl_xor_sync(0xffffffffu, su1, 1);
        su1 += __shfl_xor_sync(0xffffffffu, su1, 2);
        l0 = l0 * sc0 + su0;
        l1 = l1 * sc1 + su1;
#pragma unroll
        for (int j = 0; j < 8; j++) {
            o[j][0] *= sc0;
            o[j][1] *= sc0;
            o[j][2] *= sc1;
            o[j][3] *= sc1;
        }

#pragma unroll
        for (int kf = 0; kf < 4; kf++) {
            uint32_t ph[4], pl[4];
            split2(s[2 * kf][0], s[2 * kf][1], ph[0], pl[0]);
            split2(s[2 * kf][2], s[2 * kf][3], ph[1], pl[1]);
            split2(s[2 * kf + 1][0], s[2 * kf + 1][1], ph[2], pl[2]);
            split2(s[2 * kf + 1][2], s[2 * kf + 1][3], ph[3], pl[3]);
            uint32_t vhr[4][4], vlr[4][4];
#pragma unroll
            for (int nb = 0; nb < 4; nb++) {
                uint32_t boff = (uint32_t)(kf * 16 + lr) * R + (uint32_t)(nb * 16 + ac8) * 2;
                ldsm4t(vhr[nb], KVB + 18432 + boff);
            }
#pragma unroll
            for (int nb = 0; nb < 4; nb++) {
                mma_bf16(o[2 * nb], ph, &vhr[nb][0]);
                mma_bf16(o[2 * nb + 1], ph, &vhr[nb][2]);
                mma_bf16(o[2 * nb], pl, &vhr[nb][0]);
                mma_bf16(o[2 * nb + 1], pl, &vhr[nb][2]);
            }
#pragma unroll
            for (int nb = 0; nb < 4; nb++) {
                uint32_t boff = (uint32_t)(kf * 16 + lr) * R + (uint32_t)(nb * 16 + ac8) * 2;
                ldsm4t(vlr[nb], KVB + 27648 + boff);
            }
#pragma unroll
            for (int nb = 0; nb < 4; nb++) {
                mma_bf16(o[2 * nb], ph, &vlr[nb][0]);
                mma_bf16(o[2 * nb + 1], ph, &vlr[nb][2]);
            }
        }
        __syncthreads();
        if (kb + 2 < NKB) issueKV(kb + 2, kb & 1);
    }

    float i0 = 1.f / l0, i1 = 1.f / l1;
    const int g = lane >> 2, q = lane & 3;
    size_t base = (size_t)(qb * 128 + wid * 16) * DD + h * HD;
#pragma unroll
    for (int nj = 0; nj < 8; nj++) {
        int col = nj * 8 + q * 2;
        uint32_t hw, lw;
        split2(o[nj][0] * i0, o[nj][1] * i0, hw, lw);
        *(uint32_t*)(Oh + base + (size_t)g * DD + col) = hw;
        *(uint32_t*)(Ol + base + (size_t)g * DD + col) = lw;
        split2(o[nj][2] * i1, o[nj][3] * i1, hw, lw);
        *(uint32_t*)(Oh + base + (size_t)(g + 8) * DD + col) = hw;
        *(uint32_t*)(Ol + base + (size_t)(g + 8) * DD + col) = lw;
    }
}

// ---------------- launch -----------------------------------------------------
extern "C" void kernel_launch(void* const* d_in, const int* in_sizes, int n_in,
                              void* d_out, int out_size) {
    const float* x     = (const float*)d_in[0];
    const float* ctx   = (const float*)d_in[1];
    const float* wq    = (const float*)d_in[2];
    const float* bq    = (const float*)d_in[3];
    const float* wk    = (const float*)d_in[4];
    const float* bk    = (const float*)d_in[5];
    const float* wv    = (const float*)d_in[6];
    const float* bv    = (const float*)d_in[7];
    const float* wo    = (const float*)d_in[8];
    const float* bo    = (const float*)d_in[9];
    const float* w1    = (const float*)d_in[10];
    const float* b1    = (const float*)d_in[11];
    const float* w2    = (const float*)d_in[12];
    const float* b2    = (const float*)d_in[13];
    const float* qn_w  = (const float*)d_in[14];
    const float* qn_b  = (const float*)d_in[15];
    const float* kvn_w = (const float*)d_in[16];
    const float* kvn_b = (const float*)d_in[17];
    const float* pn_w  = (const float*)d_in[18];
    const float* pn_b  = (const float*)d_in[19];
    float* out = (float*)d_out;

#define GETP(name) \
    ushortx* name; cudaGetSymbolAddress((void**)&name, g_##name)
    GETP(xqh); GETP(xql); GETP(kvh); GETP(kvl);
    GETP(qh); GETP(ql); GETP(kh); GETP(kl); GETP(vh); GETP(vl);
    GETP(oh); GETP(ol); GETP(hlnh); GETP(hlnl); GETP(h1h); GETP(h1l);
    GETP(wqh); GETP(wql); GETP(wkh); GETP(wkl); GETP(wvh); GETP(wvl);
    GETP(woh); GETP(wol); GETP(w1h); GETP(w1l); GETP(w2h); GETP(w2l);
#undef GETP
    float* x1;
    cudaGetSymbolAddress((void**)&x1, g_x1);

    const int GSM = 3 * 37888;   // 113664
    const int FSM = 36864 + 2 * 36864;  // 110592
    cudaFuncSetAttribute((const void*)qkv_gemm,
                         cudaFuncAttributeMaxDynamicSharedMemorySize, GSM);
    cudaFuncSetAttribute((const void*)pair_gemm<1, 1, 0, 0>,
                         cudaFuncAttributeMaxDynamicSharedMemorySize, GSM);
    cudaFuncSetAttribute((const void*)pair_gemm<1, 0, 1, 1>,
                         cudaFuncAttributeMaxDynamicSharedMemorySize, GSM);
    cudaFuncSetAttribute((const void*)flash_kernel,
                         cudaFuncAttributeMaxDynamicSharedMemorySize, FSM);

    // 0. convert weights to bf16 pairs
    convert_kernel<<<(DD * DD / 4 + 255) / 256, 256>>>(wq, wqh, wql, DD * DD / 4);
    convert_kernel<<<(CC * DD / 4 + 255) / 256, 256>>>(wk, wkh, wkl, CC * DD / 4);
    convert_kernel<<<(CC * DD / 4 + 255) / 256, 256>>>(wv, wvh, wvl, CC * DD / 4);
    convert_kernel<<<(DD * DD / 4 + 255) / 256, 256>>>(wo, woh, wol, DD * DD / 4);
    convert_kernel<<<(DD * FF / 4 + 255) / 256, 256>>>(w1, w1h, w1l, DD * FF / 4);
    convert_kernel<<<(FF * DD / 4 + 255) / 256, 256>>>(w2, w2h, w2l, FF * DD / 4);

    // 1. pre-norms -> bf16 pairs
    ln_pair_kernel<DD><<<NT, 256>>>(x, qn_w, qn_b, xqh, xql);
    ln_pair_kernel<CC><<<MT, 256>>>(ctx, kvn_w, kvn_b, kvh, kvl);

    // 2. fused Q/K/V projections
    qkv_gemm<<<dim3(DD / 128, NT / 128, 3), 256, GSM>>>(
        xqh, xql, kvh, kvl, wqh, wql, wkh, wkl, wvh, wvl, bq, bk, bv,
        qh, ql, kh, kl, vh, vl);

    // 3. fused attention
    flash_kernel<<<dim3(NT / 128, NH), 256, FSM>>>(qh, ql, kh, kl, vh, vl, oh, ol);

    // 4. x1 = o @ wo + bo + x
    pair_gemm<1, 1, 0, 0><<<dim3(DD / 128, NT / 128), 256, GSM>>>(
        oh, ol, woh, wol, bo, x, x1, nullptr, nullptr, DD, DD, DD);

    // 5. MLP
    ln_pair_kernel<DD><<<NT, 256>>>(x1, pn_w, pn_b, hlnh, hlnl);
    pair_gemm<1, 0, 1, 1><<<dim3(FF / 128, NT / 128), 256, GSM>>>(
        hlnh, hlnl, w1h, w1l, b1, nullptr, nullptr, h1h, h1l, DD, DD, FF);
    pair_gemm<1, 1, 0, 0><<<dim3(DD / 128, NT / 128), 256, GSM>>>(
        h1h, h1l, w2h, w2l, b2, x1, out, nullptr, nullptr, FF, FF, DD);
}

// round 9
// speedup vs baseline: 2.7573x; 1.9298x over previous
#include <cuda_runtime.h>
#include <cuda_fp16.h>
#include <math.h>
#include <stdint.h>

#define NT 2048
#define DD 1024
#define CC 768
#define NH 16
#define HD 64
#define MT 2048
#define FF 4096

typedef unsigned short ushortx;

// ---------------- scratch (fp16 stored as ushort) -----------------------------
__device__ ushortx g_xq[NT * DD];
__device__ ushortx g_kv[MT * CC];
__device__ ushortx g_q[NT * DD];
__device__ ushortx g_k[MT * DD];
__device__ ushortx g_v[MT * DD];
__device__ ushortx g_o[NT * DD];
__device__ float   g_x1[NT * DD];
__device__ ushortx g_hln[NT * DD];
__device__ ushortx g_h1[(size_t)NT * FF];
__device__ ushortx g_wq[DD * DD];
__device__ ushortx g_wk[CC * DD];
__device__ ushortx g_wv[CC * DD];
__device__ ushortx g_wo[DD * DD];
__device__ ushortx g_w1[(size_t)DD * FF];
__device__ ushortx g_w2[(size_t)FF * DD];

// ---------------- helpers ----------------------------------------------------
__device__ __forceinline__ uint32_t smem_addr_u32(const void* p) {
    uint32_t a;
    asm("{ .reg .u64 t; cvta.to.shared.u64 t, %1; cvt.u32.u64 %0, t; }" : "=r"(a) : "l"(p));
    return a;
}
__device__ __forceinline__ void ldsm4(uint32_t* r, uint32_t addr) {
    asm volatile("ldmatrix.sync.aligned.m8n8.x4.shared.b16 {%0,%1,%2,%3}, [%4];"
                 : "=r"(r[0]), "=r"(r[1]), "=r"(r[2]), "=r"(r[3]) : "r"(addr));
}
__device__ __forceinline__ void ldsm4t(uint32_t* r, uint32_t addr) {
    asm volatile("ldmatrix.sync.aligned.m8n8.x4.trans.shared.b16 {%0,%1,%2,%3}, [%4];"
                 : "=r"(r[0]), "=r"(r[1]), "=r"(r[2]), "=r"(r[3]) : "r"(addr));
}
__device__ __forceinline__ void mma_f16(float* d, const uint32_t* a, const uint32_t* b) {
    asm volatile(
        "mma.sync.aligned.m16n8k16.row.col.f32.f16.f16.f32 "
        "{%0,%1,%2,%3}, {%4,%5,%6,%7}, {%8,%9}, {%0,%1,%2,%3};"
        : "+f"(d[0]), "+f"(d[1]), "+f"(d[2]), "+f"(d[3])
        : "r"(a[0]), "r"(a[1]), "r"(a[2]), "r"(a[3]), "r"(b[0]), "r"(b[1]));
}
__device__ __forceinline__ uint32_t packh2(float x, float y) {
    __half2 h = __floats2half2_rn(x, y);
    return *(uint32_t*)&h;
}
__device__ __forceinline__ void cpa16(uint32_t d, const void* g) {
    asm volatile("cp.async.cg.shared.global [%0], [%1], 16;" :: "r"(d), "l"(g));
}
__device__ __forceinline__ void cpcommit() { asm volatile("cp.async.commit_group;" ::: "memory"); }
template <int N>
__device__ __forceinline__ void cpwait() {
    asm volatile("cp.async.wait_group %0;" :: "n"(N) : "memory");
}

// ---------------- convert fp32 -> fp16 ----------------------------------------
__global__ __launch_bounds__(256) void convert_kernel(
    const float* __restrict__ s, ushortx* __restrict__ h, int n4) {
    int i = blockIdx.x * 256 + threadIdx.x;
    if (i >= n4) return;
    float4 f = ((const float4*)s)[i];
    ((uint2*)h)[i] = make_uint2(packh2(f.x, f.y), packh2(f.z, f.w));
}

// ---------------- layernorm -> fp16 -------------------------------------------
__device__ __forceinline__ float block_reduce_sum(float v) {
    __shared__ float sh[8];
    int tid = threadIdx.x;
#pragma unroll
    for (int o = 16; o > 0; o >>= 1) v += __shfl_down_sync(0xffffffffu, v, o);
    if ((tid & 31) == 0) sh[tid >> 5] = v;
    __syncthreads();
    if (tid < 32) {
        v = (tid < 8) ? sh[tid] : 0.f;
#pragma unroll
        for (int o = 4; o > 0; o >>= 1) v += __shfl_down_sync(0xffffffffu, v, o);
        if (tid == 0) sh[0] = v;
    }
    __syncthreads();
    float r = sh[0];
    __syncthreads();
    return r;
}

template <int DIM>
__global__ __launch_bounds__(256) void ln_half_kernel(
    const float* __restrict__ x, const float* __restrict__ w, const float* __restrict__ b,
    ushortx* __restrict__ oh) {
    const float* xr = x + (size_t)blockIdx.x * DIM;
    int tid = threadIdx.x;
    float4 f = make_float4(0.f, 0.f, 0.f, 0.f);
    if (tid < DIM / 4) f = ((const float4*)xr)[tid];
    float s = f.x + f.y + f.z + f.w;
    float mean = block_reduce_sum(s) * (1.f / DIM);
    float vv = 0.f;
    if (tid < DIM / 4) {
        float c0 = f.x - mean, c1 = f.y - mean, c2 = f.z - mean, c3 = f.w - mean;
        vv = c0 * c0 + c1 * c1 + c2 * c2 + c3 * c3;
    }
    float var = block_reduce_sum(vv) * (1.f / DIM);
    float inv = rsqrtf(var + 1e-12f);
    if (tid < DIM / 4) {
        float4 w4 = ((const float4*)w)[tid];
        float4 b4 = ((const float4*)b)[tid];
        float o0 = (f.x - mean) * inv * w4.x + b4.x;
        float o1 = (f.y - mean) * inv * w4.y + b4.y;
        float o2 = (f.z - mean) * inv * w4.z + b4.z;
        float o3 = (f.w - mean) * inv * w4.w + b4.w;
        ((uint2*)(oh + (size_t)blockIdx.x * DIM))[tid] =
            make_uint2(packh2(o0, o1), packh2(o2, o3));
    }
}

// ---------------- fp16 GEMM core (4-stage cp.async) ----------------------------
// C[128x128] tile at (bx,by). A fp16 [M,K] lda=K; B fp16 [K,N] ldb=N.
template <int BIAS, int RES, int GELU, int OUTH>
__device__ __forceinline__ void gemm_core(
    const ushortx* __restrict__ A, const ushortx* __restrict__ B,
    const float* __restrict__ bias, const float* __restrict__ Res,
    float* __restrict__ Cf, ushortx* __restrict__ Ch,
    int K, int lda, int ldb, int bx, int by) {
    constexpr int RA = 80, RB = 272;
    constexpr int ASZ = 128 * RA;   // 10240
    constexpr int BSZ = 32 * RB;    // 8704
    constexpr int STAGE = ASZ + BSZ;  // 18944

    extern __shared__ char sm[];
    const int tid = threadIdx.x, lane = tid & 31, wid = tid >> 5;
    const int wm = wid & 1, wn = wid >> 1;
    const uint32_t sb = smem_addr_u32(sm);

    const ushortx* Ab = A + (size_t)by * 128 * lda;
    const ushortx* Bb = B + (size_t)bx * 128;

    auto issue = [&](int k0, int buf) {
        uint32_t d = sb + buf * STAGE;
        {   // A tile: 128 rows x 4 chunks of 16B = 512; 2 per thread
            int r = tid >> 1, s = (tid & 1) * 2;
            uint32_t dd = d + (uint32_t)(r * RA + s * 16);
            size_t so = (size_t)r * lda + k0 + s * 8;
            cpa16(dd, Ab + so);
            cpa16(dd + 16, Ab + so + 8);
        }
        {   // B tile: 32 rows x 16 chunks = 512; 2 per thread
            int kr = tid >> 3, s = (tid & 7) * 2;
            uint32_t dd = d + ASZ + (uint32_t)(kr * RB + s * 16);
            size_t so = (size_t)(k0 + kr) * ldb + s * 8;
            cpa16(dd, Bb + so);
            cpa16(dd + 16, Bb + so + 8);
        }
        cpcommit();
    };

    float acc[4][4][4];
#pragma unroll
    for (int i = 0; i < 4; i++)
#pragma unroll
        for (int j = 0; j < 4; j++)
#pragma unroll
            for (int q = 0; q < 4; q++) acc[i][j][q] = 0.f;

    const int lr = lane & 15;
    const int ac8 = (lane >> 4) << 3;

    auto domma = [&](int buf) {
        const uint32_t ab = sb + buf * STAGE;
        const uint32_t bb = ab + ASZ;
#pragma unroll
        for (int kk = 0; kk < 2; kk++) {
            uint32_t bf[2][4];
#pragma unroll
            for (int nb = 0; nb < 2; nb++) {
                uint32_t boff = (uint32_t)(kk * 16 + lr) * RB +
                                (uint32_t)(wn * 32 + nb * 16 + ac8) * 2;
                ldsm4t(bf[nb], bb + boff);
            }
#pragma unroll
            for (int mi = 0; mi < 4; mi++) {
                uint32_t aoff = (uint32_t)(wm * 64 + mi * 16 + lr) * RA +
                                (uint32_t)(kk * 16 + ac8) * 2;
                uint32_t af[4];
                ldsm4(af, ab + aoff);
#pragma unroll
                for (int nb = 0; nb < 2; nb++) {
                    mma_f16(acc[mi][2 * nb], af, &bf[nb][0]);
                    mma_f16(acc[mi][2 * nb + 1], af, &bf[nb][2]);
                }
            }
        }
    };

    const int T = K >> 5;
    issue(0, 0);
    issue(32, 1);
    issue(64, 2);
#pragma unroll 1
    for (int t = 0; t < T; t++) {
        if (t + 3 <= T) cpwait<2>();
        else if (t + 2 <= T) cpwait<1>();
        else cpwait<0>();
        __syncthreads();
        if (t + 3 < T) issue((t + 3) * 32, (t + 3) & 3);
        domma(t & 3);
    }

    // epilogue
    const int g = lane >> 2, q = lane & 3;
    const size_t c0 = (size_t)by * 128 * ldb + (size_t)bx * 128;
#pragma unroll
    for (int mi = 0; mi < 4; mi++)
#pragma unroll
        for (int nj = 0; nj < 4; nj++) {
            int col = wn * 32 + nj * 8 + q * 2;
            float bv0 = BIAS ? bias[bx * 128 + col] : 0.f;
            float bv1 = BIAS ? bias[bx * 128 + col + 1] : 0.f;
#pragma unroll
            for (int rr = 0; rr < 2; rr++) {
                int row = wm * 64 + mi * 16 + g + rr * 8;
                float v0 = acc[mi][nj][rr * 2] + bv0;
                float v1 = acc[mi][nj][rr * 2 + 1] + bv1;
                if (RES) {
                    const float* rp = Res + c0 + (size_t)row * ldb + col;
                    v0 += rp[0];
                    v1 += rp[1];
                }
                if (GELU) {
                    float i0 = 0.7978845608028654f * (v0 + 0.044715f * v0 * v0 * v0);
                    v0 = 0.5f * v0 * (1.f + tanhf(i0));
                    float i1 = 0.7978845608028654f * (v1 + 0.044715f * v1 * v1 * v1);
                    v1 = 0.5f * v1 * (1.f + tanhf(i1));
                }
                if (OUTH) {
                    *(uint32_t*)(Ch + c0 + (size_t)row * ldb + col) = packh2(v0, v1);
                } else {
                    *(float2*)(Cf + c0 + (size_t)row * ldb + col) = make_float2(v0, v1);
                }
            }
        }
}

template <int BIAS, int RES, int GELU, int OUTH>
__global__ __launch_bounds__(256, 2) void half_gemm(
    const ushortx* A, const ushortx* B, const float* bias, const float* Res,
    float* Cf, ushortx* Ch, int K, int lda, int ldb) {
    gemm_core<BIAS, RES, GELU, OUTH>(A, B, bias, Res, Cf, Ch, K, lda, ldb,
                                     blockIdx.x, blockIdx.y);
}

// fused QKV
__global__ __launch_bounds__(256, 2) void qkv_gemm(
    const ushortx* xq, const ushortx* kv,
    const ushortx* wq, const ushortx* wk, const ushortx* wv,
    const float* bq, const float* bk, const float* bv,
    ushortx* q, ushortx* k, ushortx* v) {
    int z = blockIdx.z;
    const ushortx *A, *B;
    const float* bias;
    ushortx* C;
    int K, lda;
    if (z == 0) { A = xq; B = wq; bias = bq; C = q; K = DD; lda = DD; }
    else if (z == 1) { A = kv; B = wk; bias = bk; C = k; K = CC; lda = CC; }
    else { A = kv; B = wv; bias = bv; C = v; K = CC; lda = CC; }
    gemm_core<1, 0, 0, 1>(A, B, bias, nullptr, nullptr, C, K, lda, DD,
                          blockIdx.x, blockIdx.y);
}

// ---------------- flash attention (fp16, double-buffered KV) -------------------
__global__ __launch_bounds__(256, 2) void flash_kernel(
    const ushortx* __restrict__ Q, const ushortx* __restrict__ K,
    const ushortx* __restrict__ V, ushortx* __restrict__ O) {
    constexpr int R = 144;
    constexpr int QO = 0;
    constexpr int KVB0 = 18432, KVSZ = 18432;  // per-stage: K 9216, V 9216
    constexpr int NKB = MT / 64;

    extern __shared__ char sm[];
    const int tid = threadIdx.x, lane = tid & 31, wid = tid >> 5;
    const int h = blockIdx.y, qb = blockIdx.x;
    const uint32_t sb = smem_addr_u32(sm);

    const ushortx* Qg = Q + (size_t)qb * 128 * DD + h * HD;
    const ushortx* Kg = K + h * HD;
    const ushortx* Vg = V + h * HD;

    // Q: 128 rows x 8 chunks (16B each) = 1024 chunks, joins first commit group
#pragma unroll
    for (int j = 0; j < 4; j++) {
        int i = tid + j * 256;
        int r = i >> 3, s = i & 7;
        uint32_t dd = sb + QO + (uint32_t)(r * R + s * 16);
        cpa16(dd, Qg + (size_t)r * DD + s * 8);
    }
    // KV: 64 rows x 8 chunks each for K and V (512 chunks apiece)
    auto issueKV = [&](int kb, int buf) {
        uint32_t base = sb + KVB0 + (uint32_t)buf * KVSZ;
#pragma unroll
        for (int j = 0; j < 2; j++) {
            int i = tid + j * 256;
            int r = i >> 3, s = i & 7;
            uint32_t dd = base + (uint32_t)(r * R + s * 16);
            size_t so = (size_t)(kb * 64 + r) * DD + s * 8;
            cpa16(dd, Kg + so);
            cpa16(dd + 9216, Vg + so);
        }
        cpcommit();
    };
    issueKV(0, 0);
    issueKV(1, 1);

    float o[8][4];
#pragma unroll
    for (int i = 0; i < 8; i++)
#pragma unroll
        for (int j = 0; j < 4; j++) o[i][j] = 0.f;
    float m0 = -INFINITY, m1 = -INFINITY, l0 = 0.f, l1 = 0.f;

    const int lr = lane & 15;
    const int ac8 = (lane >> 4) << 3;
    const int bn = (lane & 7) + ((lane >> 4) << 3);
    const int bc8 = ((lane >> 3) & 1) << 3;

    for (int kb = 0; kb < NKB; kb++) {
        if (kb < NKB - 1) cpwait<1>();
        else cpwait<0>();
        __syncthreads();
        const uint32_t KVB = sb + KVB0 + (uint32_t)(kb & 1) * KVSZ;

        float s[8][4];
#pragma unroll
        for (int i = 0; i < 8; i++)
#pragma unroll
            for (int j = 0; j < 4; j++) s[i][j] = 0.f;
#pragma unroll
        for (int kf = 0; kf < 4; kf++) {
            uint32_t aoff = (uint32_t)(wid * 16 + lr) * R + (uint32_t)(kf * 16 + ac8) * 2;
            uint32_t qf[4], kfr[4][4];
            ldsm4(qf, sb + QO + aoff);
#pragma unroll
            for (int nb = 0; nb < 4; nb++) {
                uint32_t boff = (uint32_t)(nb * 16 + bn) * R + (uint32_t)(kf * 16 + bc8) * 2;
                ldsm4(kfr[nb], KVB + boff);
            }
#pragma unroll
            for (int nb = 0; nb < 4; nb++) {
                mma_f16(s[2 * nb], qf, &kfr[nb][0]);
                mma_f16(s[2 * nb + 1], qf, &kfr[nb][2]);
            }
        }

        float mx0 = -INFINITY, mx1 = -INFINITY;
#pragma unroll
        for (int j = 0; j < 8; j++) {
            mx0 = fmaxf(mx0, fmaxf(s[j][0], s[j][1]));
            mx1 = fmaxf(mx1, fmaxf(s[j][2], s[j][3]));
        }
        mx0 = fmaxf(mx0, __shfl_xor_sync(0xffffffffu, mx0, 1));
        mx0 = fmaxf(mx0, __shfl_xor_sync(0xffffffffu, mx0, 2));
        mx1 = fmaxf(mx1, __shfl_xor_sync(0xffffffffu, mx1, 1));
        mx1 = fmaxf(mx1, __shfl_xor_sync(0xffffffffu, mx1, 2));
        float m0n = fmaxf(m0, mx0), m1n = fmaxf(m1, mx1);
        float sc0 = __expf((m0 - m0n) * 0.125f);
        float sc1 = __expf((m1 - m1n) * 0.125f);
        m0 = m0n;
        m1 = m1n;
        float su0 = 0.f, su1 = 0.f;
#pragma unroll
        for (int j = 0; j < 8; j++) {
            s[j][0] = __expf((s[j][0] - m0) * 0.125f);
            s[j][1] = __expf((s[j][1] - m0) * 0.125f);
            s[j][2] = __expf((s[j][2] - m1) * 0.125f);
            s[j][3] = __expf((s[j][3] - m1) * 0.125f);
            su0 += s[j][0] + s[j][1];
            su1 += s[j][2] + s[j][3];
        }
        su0 += __shfl_xor_sync(0xffffffffu, su0, 1);
        su0 += __shfl_xor_sync(0xffffffffu, su0, 2);
        su1 += __shfl_xor_sync(0xffffffffu, su1, 1);
        su1 += __shfl_xor_sync(0xffffffffu, su1, 2);
        l0 = l0 * sc0 + su0;
        l1 = l1 * sc1 + su1;
#pragma unroll
        for (int j = 0; j < 8; j++) {
            o[j][0] *= sc0;
            o[j][1] *= sc0;
            o[j][2] *= sc1;
            o[j][3] *= sc1;
        }

#pragma unroll
        for (int kf = 0; kf < 4; kf++) {
            uint32_t ph[4];
            ph[0] = packh2(s[2 * kf][0], s[2 * kf][1]);
            ph[1] = packh2(s[2 * kf][2], s[2 * kf][3]);
            ph[2] = packh2(s[2 * kf + 1][0], s[2 * kf + 1][1]);
            ph[3] = packh2(s[2 * kf + 1][2], s[2 * kf + 1][3]);
            uint32_t vf[4][4];
#pragma unroll
            for (int nb = 0; nb < 4; nb++) {
                uint32_t boff = (uint32_t)(kf * 16 + lr) * R + (uint32_t)(nb * 16 + ac8) * 2;
                ldsm4t(vf[nb], KVB + 9216 + boff);
            }
#pragma unroll
            for (int nb = 0; nb < 4; nb++) {
                mma_f16(o[2 * nb], ph, &vf[nb][0]);
                mma_f16(o[2 * nb + 1], ph, &vf[nb][2]);
            }
        }
        __syncthreads();
        if (kb + 2 < NKB) issueKV(kb + 2, kb & 1);
    }

    float i0 = 1.f / l0, i1 = 1.f / l1;
    const int g = lane >> 2, q = lane & 3;
    size_t base = (size_t)(qb * 128 + wid * 16) * DD + h * HD;
#pragma unroll
    for (int nj = 0; nj < 8; nj++) {
        int col = nj * 8 + q * 2;
        *(uint32_t*)(O + base + (size_t)g * DD + col) = packh2(o[nj][0] * i0, o[nj][1] * i0);
        *(uint32_t*)(O + base + (size_t)(g + 8) * DD + col) =
            packh2(o[nj][2] * i1, o[nj][3] * i1);
    }
}

// ---------------- launch -----------------------------------------------------
extern "C" void kernel_launch(void* const* d_in, const int* in_sizes, int n_in,
                              void* d_out, int out_size) {
    const float* x     = (const float*)d_in[0];
    const float* ctx   = (const float*)d_in[1];
    const float* wq    = (const float*)d_in[2];
    const float* bq    = (const float*)d_in[3];
    const float* wk    = (const float*)d_in[4];
    const float* bk    = (const float*)d_in[5];
    const float* wv    = (const float*)d_in[6];
    const float* bv    = (const float*)d_in[7];
    const float* wo    = (const float*)d_in[8];
    const float* bo    = (const float*)d_in[9];
    const float* w1    = (const float*)d_in[10];
    const float* b1    = (const float*)d_in[11];
    const float* w2    = (const float*)d_in[12];
    const float* b2    = (const float*)d_in[13];
    const float* qn_w  = (const float*)d_in[14];
    const float* qn_b  = (const float*)d_in[15];
    const float* kvn_w = (const float*)d_in[16];
    const float* kvn_b = (const float*)d_in[17];
    const float* pn_w  = (const float*)d_in[18];
    const float* pn_b  = (const float*)d_in[19];
    float* out = (float*)d_out;

#define GETP(name) \
    ushortx* name##p; cudaGetSymbolAddress((void**)&name##p, g_##name)
    GETP(xq); GETP(kv); GETP(q); GETP(k); GETP(v); GETP(o); GETP(hln); GETP(h1);
    GETP(wq); GETP(wk); GETP(wv); GETP(wo); GETP(w1); GETP(w2);
#undef GETP
    float* x1;
    cudaGetSymbolAddress((void**)&x1, g_x1);

    const int GSM = 4 * 18944;   // 75776
    const int FSM = 18432 + 2 * 18432;  // 55296
    cudaFuncSetAttribute((const void*)qkv_gemm,
                         cudaFuncAttributeMaxDynamicSharedMemorySize, GSM);
    cudaFuncSetAttribute((const void*)half_gemm<1, 1, 0, 0>,
                         cudaFuncAttributeMaxDynamicSharedMemorySize, GSM);
    cudaFuncSetAttribute((const void*)half_gemm<1, 0, 1, 1>,
                         cudaFuncAttributeMaxDynamicSharedMemorySize, GSM);
    cudaFuncSetAttribute((const void*)flash_kernel,
                         cudaFuncAttributeMaxDynamicSharedMemorySize, FSM);

    // 0. convert weights to fp16
    convert_kernel<<<(DD * DD / 4 + 255) / 256, 256>>>(wq, wqp, DD * DD / 4);
    convert_kernel<<<(CC * DD / 4 + 255) / 256, 256>>>(wk, wkp, CC * DD / 4);
    convert_kernel<<<(CC * DD / 4 + 255) / 256, 256>>>(wv, wvp, CC * DD / 4);
    convert_kernel<<<(DD * DD / 4 + 255) / 256, 256>>>(wo, wop, DD * DD / 4);
    convert_kernel<<<(DD * FF / 4 + 255) / 256, 256>>>(w1, w1p, DD * FF / 4);
    convert_kernel<<<(FF * DD / 4 + 255) / 256, 256>>>(w2, w2p, FF * DD / 4);

    // 1. pre-norms -> fp16
    ln_half_kernel<DD><<<NT, 256>>>(x, qn_w, qn_b, xqp);
    ln_half_kernel<CC><<<MT, 256>>>(ctx, kvn_w, kvn_b, kvp);

    // 2. fused Q/K/V projections
    qkv_gemm<<<dim3(DD / 128, NT / 128, 3), 256, GSM>>>(
        xqp, kvp, wqp, wkp, wvp, bq, bk, bv, qp, kp, vp);

    // 3. fused attention
    flash_kernel<<<dim3(NT / 128, NH), 256, FSM>>>(qp, kp, vp, op);

    // 4. x1 = o @ wo + bo + x
    half_gemm<1, 1, 0, 0><<<dim3(DD / 128, NT / 128), 256, GSM>>>(
        op, wop, bo, x, x1, nullptr, DD, DD, DD);

    // 5. MLP
    ln_half_kernel<DD><<<NT, 256>>>(x1, pn_w, pn_b, hlnp);
    half_gemm<1, 0, 1, 1><<<dim3(FF / 128, NT / 128), 256, GSM>>>(
        hlnp, w1p, b1, nullptr, nullptr, h1p, DD, DD, FF);
    half_gemm<1, 1, 0, 0><<<dim3(DD / 128, NT / 128), 256, GSM>>>(
        h1p, w2p, b2, x1, out, nullptr, FF, FF, DD);
}

// round 10
// speedup vs baseline: 2.9752x; 1.0790x over previous
#include <cuda_runtime.h>
#include <cuda_fp16.h>
#include <math.h>
#include <stdint.h>

#define NT 2048
#define DD 1024
#define CC 768
#define NH 16
#define HD 64
#define MT 2048
#define FF 4096

typedef unsigned short ushortx;

// ---------------- scratch (fp16 stored as ushort) -----------------------------
__device__ ushortx g_xq[NT * DD];
__device__ ushortx g_kv[MT * CC];
__device__ ushortx g_q[NT * DD];
__device__ ushortx g_k[MT * DD];
__device__ ushortx g_v[MT * DD];
__device__ ushortx g_o[NT * DD];
__device__ float   g_x1[NT * DD];
__device__ ushortx g_hln[NT * DD];
__device__ ushortx g_h1[(size_t)NT * FF];
__device__ ushortx g_wq[DD * DD];
__device__ ushortx g_wk[CC * DD];
__device__ ushortx g_wv[CC * DD];
__device__ ushortx g_wo[DD * DD];
__device__ ushortx g_w1[(size_t)DD * FF];
__device__ ushortx g_w2[(size_t)FF * DD];

// ---------------- helpers ----------------------------------------------------
__device__ __forceinline__ uint32_t smem_addr_u32(const void* p) {
    uint32_t a;
    asm("{ .reg .u64 t; cvta.to.shared.u64 t, %1; cvt.u32.u64 %0, t; }" : "=r"(a) : "l"(p));
    return a;
}
__device__ __forceinline__ void ldsm4(uint32_t* r, uint32_t addr) {
    asm volatile("ldmatrix.sync.aligned.m8n8.x4.shared.b16 {%0,%1,%2,%3}, [%4];"
                 : "=r"(r[0]), "=r"(r[1]), "=r"(r[2]), "=r"(r[3]) : "r"(addr));
}
__device__ __forceinline__ void ldsm4t(uint32_t* r, uint32_t addr) {
    asm volatile("ldmatrix.sync.aligned.m8n8.x4.trans.shared.b16 {%0,%1,%2,%3}, [%4];"
                 : "=r"(r[0]), "=r"(r[1]), "=r"(r[2]), "=r"(r[3]) : "r"(addr));
}
__device__ __forceinline__ void mma_f16(float* d, const uint32_t* a, const uint32_t* b) {
    asm volatile(
        "mma.sync.aligned.m16n8k16.row.col.f32.f16.f16.f32 "
        "{%0,%1,%2,%3}, {%4,%5,%6,%7}, {%8,%9}, {%0,%1,%2,%3};"
        : "+f"(d[0]), "+f"(d[1]), "+f"(d[2]), "+f"(d[3])
        : "r"(a[0]), "r"(a[1]), "r"(a[2]), "r"(a[3]), "r"(b[0]), "r"(b[1]));
}
__device__ __forceinline__ uint32_t packh2(float x, float y) {
    __half2 h = __floats2half2_rn(x, y);
    return *(uint32_t*)&h;
}
__device__ __forceinline__ void cpa16(uint32_t d, const void* g) {
    asm volatile("cp.async.cg.shared.global [%0], [%1], 16;" :: "r"(d), "l"(g));
}
__device__ __forceinline__ void cpcommit() { asm volatile("cp.async.commit_group;" ::: "memory"); }
template <int N>
__device__ __forceinline__ void cpwait() {
    asm volatile("cp.async.wait_group %0;" :: "n"(N) : "memory");
}

// ---------------- convert fp32 -> fp16 ----------------------------------------
__global__ __launch_bounds__(256) void convert_kernel(
    const float* __restrict__ s, ushortx* __restrict__ h, int n4) {
    int i = blockIdx.x * 256 + threadIdx.x;
    if (i >= n4) return;
    float4 f = ((const float4*)s)[i];
    ((uint2*)h)[i] = make_uint2(packh2(f.x, f.y), packh2(f.z, f.w));
}

// ---------------- layernorm -> fp16 -------------------------------------------
__device__ __forceinline__ float block_reduce_sum(float v) {
    __shared__ float sh[8];
    int tid = threadIdx.x;
#pragma unroll
    for (int o = 16; o > 0; o >>= 1) v += __shfl_down_sync(0xffffffffu, v, o);
    if ((tid & 31) == 0) sh[tid >> 5] = v;
    __syncthreads();
    if (tid < 32) {
        v = (tid < 8) ? sh[tid] : 0.f;
#pragma unroll
        for (int o = 4; o > 0; o >>= 1) v += __shfl_down_sync(0xffffffffu, v, o);
        if (tid == 0) sh[0] = v;
    }
    __syncthreads();
    float r = sh[0];
    __syncthreads();
    return r;
}

template <int DIM>
__global__ __launch_bounds__(256) void ln_half_kernel(
    const float* __restrict__ x, const float* __restrict__ w, const float* __restrict__ b,
    ushortx* __restrict__ oh) {
    const float* xr = x + (size_t)blockIdx.x * DIM;
    int tid = threadIdx.x;
    float4 f = make_float4(0.f, 0.f, 0.f, 0.f);
    if (tid < DIM / 4) f = ((const float4*)xr)[tid];
    float s = f.x + f.y + f.z + f.w;
    float mean = block_reduce_sum(s) * (1.f / DIM);
    float vv = 0.f;
    if (tid < DIM / 4) {
        float c0 = f.x - mean, c1 = f.y - mean, c2 = f.z - mean, c3 = f.w - mean;
        vv = c0 * c0 + c1 * c1 + c2 * c2 + c3 * c3;
    }
    float var = block_reduce_sum(vv) * (1.f / DIM);
    float inv = rsqrtf(var + 1e-12f);
    if (tid < DIM / 4) {
        float4 w4 = ((const float4*)w)[tid];
        float4 b4 = ((const float4*)b)[tid];
        float o0 = (f.x - mean) * inv * w4.x + b4.x;
        float o1 = (f.y - mean) * inv * w4.y + b4.y;
        float o2 = (f.z - mean) * inv * w4.z + b4.z;
        float o3 = (f.w - mean) * inv * w4.w + b4.w;
        ((uint2*)(oh + (size_t)blockIdx.x * DIM))[tid] =
            make_uint2(packh2(o0, o1), packh2(o2, o3));
    }
}

// ---------------- fp16 GEMM core (128 thr, 4 warps, warp tile 64x64) -----------
// C[128x128] tile at (bx,by). A fp16 [M,K] lda=K; B fp16 [K,N] ldb=N.
template <int BIAS, int RES, int GELU, int OUTH>
__device__ __forceinline__ void gemm_core(
    const ushortx* __restrict__ A, const ushortx* __restrict__ B,
    const float* __restrict__ bias, const float* __restrict__ Res,
    float* __restrict__ Cf, ushortx* __restrict__ Ch,
    int K, int lda, int ldb, int bx, int by) {
    constexpr int RA = 80, RB = 272;
    constexpr int ASZ = 128 * RA;   // 10240
    constexpr int BSZ = 32 * RB;    // 8704
    constexpr int STAGE = ASZ + BSZ;  // 18944

    extern __shared__ char sm[];
    const int tid = threadIdx.x, lane = tid & 31, wid = tid >> 5;  // 4 warps
    const int wm = wid & 1, wn = wid >> 1;                         // 2x2
    const uint32_t sb = smem_addr_u32(sm);

    const ushortx* Ab = A + (size_t)by * 128 * lda;
    const ushortx* Bb = B + (size_t)bx * 128;

    auto issue = [&](int k0, int buf) {
        uint32_t d = sb + buf * STAGE;
#pragma unroll
        for (int j = 0; j < 4; j++) {   // A: 512 chunks, 4/thread
            int i = tid + j * 128;
            int r = i >> 2, s = i & 3;
            cpa16(d + (uint32_t)(r * RA + s * 16), Ab + (size_t)r * lda + k0 + s * 8);
        }
#pragma unroll
        for (int j = 0; j < 4; j++) {   // B: 512 chunks, 4/thread
            int i = tid + j * 128;
            int kr = i >> 4, s = i & 15;
            cpa16(d + ASZ + (uint32_t)(kr * RB + s * 16),
                  Bb + (size_t)(k0 + kr) * ldb + s * 8);
        }
        cpcommit();
    };

    float acc[4][8][4];
#pragma unroll
    for (int i = 0; i < 4; i++)
#pragma unroll
        for (int j = 0; j < 8; j++)
#pragma unroll
            for (int q = 0; q < 4; q++) acc[i][j][q] = 0.f;

    const int lr = lane & 15;
    const int ac8 = (lane >> 4) << 3;

    auto domma = [&](int buf) {
        const uint32_t ab = sb + buf * STAGE;
        const uint32_t bb = ab + ASZ;
#pragma unroll
        for (int kk = 0; kk < 2; kk++) {
            uint32_t bf[4][4];
#pragma unroll
            for (int nj = 0; nj < 4; nj++) {
                uint32_t boff = (uint32_t)(kk * 16 + lr) * RB +
                                (uint32_t)(wn * 64 + nj * 16 + ac8) * 2;
                ldsm4t(bf[nj], bb + boff);
            }
#pragma unroll
            for (int mi = 0; mi < 4; mi++) {
                uint32_t aoff = (uint32_t)(wm * 64 + mi * 16 + lr) * RA +
                                (uint32_t)(kk * 16 + ac8) * 2;
                uint32_t af[4];
                ldsm4(af, ab + aoff);
#pragma unroll
                for (int nj = 0; nj < 4; nj++) {
                    mma_f16(acc[mi][2 * nj], af, &bf[nj][0]);
                    mma_f16(acc[mi][2 * nj + 1], af, &bf[nj][2]);
                }
            }
        }
    };

    const int T = K >> 5;
    issue(0, 0);
    issue(32, 1);
    issue(64, 2);
#pragma unroll 1
    for (int t = 0; t < T; t++) {
        if (t + 3 <= T) cpwait<2>();
        else if (t + 2 <= T) cpwait<1>();
        else cpwait<0>();
        __syncthreads();
        if (t + 3 < T) issue((t + 3) * 32, (t + 3) & 3);
        domma(t & 3);
    }

    // epilogue
    const int g = lane >> 2, q = lane & 3;
    const size_t c0 = (size_t)by * 128 * ldb + (size_t)bx * 128;
#pragma unroll
    for (int mi = 0; mi < 4; mi++)
#pragma unroll
        for (int nj = 0; nj < 8; nj++) {
            int col = wn * 64 + nj * 8 + q * 2;
            float bv0 = BIAS ? bias[bx * 128 + col] : 0.f;
            float bv1 = BIAS ? bias[bx * 128 + col + 1] : 0.f;
#pragma unroll
            for (int rr = 0; rr < 2; rr++) {
                int row = wm * 64 + mi * 16 + g + rr * 8;
                float v0 = acc[mi][nj][rr * 2] + bv0;
                float v1 = acc[mi][nj][rr * 2 + 1] + bv1;
                if (RES) {
                    const float* rp = Res + c0 + (size_t)row * ldb + col;
                    v0 += rp[0];
                    v1 += rp[1];
                }
                if (GELU) {
                    float i0 = 0.7978845608028654f * (v0 + 0.044715f * v0 * v0 * v0);
                    v0 = 0.5f * v0 * (1.f + tanhf(i0));
                    float i1 = 0.7978845608028654f * (v1 + 0.044715f * v1 * v1 * v1);
                    v1 = 0.5f * v1 * (1.f + tanhf(i1));
                }
                if (OUTH) {
                    *(uint32_t*)(Ch + c0 + (size_t)row * ldb + col) = packh2(v0, v1);
                } else {
                    *(float2*)(Cf + c0 + (size_t)row * ldb + col) = make_float2(v0, v1);
                }
            }
        }
}

template <int BIAS, int RES, int GELU, int OUTH>
__global__ __launch_bounds__(128, 2) void half_gemm(
    const ushortx* A, const ushortx* B, const float* bias, const float* Res,
    float* Cf, ushortx* Ch, int K, int lda, int ldb) {
    gemm_core<BIAS, RES, GELU, OUTH>(A, B, bias, Res, Cf, Ch, K, lda, ldb,
                                     blockIdx.x, blockIdx.y);
}

// fused QKV
__global__ __launch_bounds__(128, 2) void qkv_gemm(
    const ushortx* xq, const ushortx* kv,
    const ushortx* wq, const ushortx* wk, const ushortx* wv,
    const float* bq, const float* bk, const float* bv,
    ushortx* q, ushortx* k, ushortx* v) {
    int z = blockIdx.z;
    const ushortx *A, *B;
    const float* bias;
    ushortx* C;
    int K, lda;
    if (z == 0) { A = xq; B = wq; bias = bq; C = q; K = DD; lda = DD; }
    else if (z == 1) { A = kv; B = wk; bias = bk; C = k; K = CC; lda = CC; }
    else { A = kv; B = wv; bias = bv; C = v; K = CC; lda = CC; }
    gemm_core<1, 0, 0, 1>(A, B, bias, nullptr, nullptr, C, K, lda, DD,
                          blockIdx.x, blockIdx.y);
}

// ---------------- flash attention (128 thr, 4 warps x 32 query rows) -----------
__global__ __launch_bounds__(128, 2) void flash_kernel(
    const ushortx* __restrict__ Q, const ushortx* __restrict__ K,
    const ushortx* __restrict__ V, ushortx* __restrict__ O) {
    constexpr int R = 144;
    constexpr int QO = 0;
    constexpr int KVB0 = 18432, KVSZ = 18432;  // per-stage: K 9216, V 9216
    constexpr int NKB = MT / 64;

    extern __shared__ char sm[];
    const int tid = threadIdx.x, lane = tid & 31, wid = tid >> 5;  // 4 warps
    const int h = blockIdx.y, qb = blockIdx.x;
    const uint32_t sb = smem_addr_u32(sm);

    const ushortx* Qg = Q + (size_t)qb * 128 * DD + h * HD;
    const ushortx* Kg = K + h * HD;
    const ushortx* Vg = V + h * HD;

    // Q: 128 rows x 8 chunks = 1024 chunks, 8/thread — joins first commit group
#pragma unroll
    for (int j = 0; j < 8; j++) {
        int i = tid + j * 128;
        int r = i >> 3, s = i & 7;
        cpa16(sb + QO + (uint32_t)(r * R + s * 16), Qg + (size_t)r * DD + s * 8);
    }
    // KV: 64 rows x 8 chunks each (512 chunks apiece), 4/thread
    auto issueKV = [&](int kb, int buf) {
        uint32_t base = sb + KVB0 + (uint32_t)buf * KVSZ;
#pragma unroll
        for (int j = 0; j < 4; j++) {
            int i = tid + j * 128;
            int r = i >> 3, s = i & 7;
            uint32_t dd = base + (uint32_t)(r * R + s * 16);
            size_t so = (size_t)(kb * 64 + r) * DD + s * 8;
            cpa16(dd, Kg + so);
            cpa16(dd + 9216, Vg + so);
        }
        cpcommit();
    };
    issueKV(0, 0);
    issueKV(1, 1);

    float o[2][8][4];
#pragma unroll
    for (int mt = 0; mt < 2; mt++)
#pragma unroll
        for (int j = 0; j < 8; j++)
#pragma unroll
            for (int q = 0; q < 4; q++) o[mt][j][q] = 0.f;
    float m[2][2] = {{-INFINITY, -INFINITY}, {-INFINITY, -INFINITY}};
    float l[2][2] = {{0.f, 0.f}, {0.f, 0.f}};

    const int lr = lane & 15;
    const int ac8 = (lane >> 4) << 3;
    const int bn = (lane & 7) + ((lane >> 4) << 3);
    const int bc8 = ((lane >> 3) & 1) << 3;

    for (int kb = 0; kb < NKB; kb++) {
        if (kb < NKB - 1) cpwait<1>();
        else cpwait<0>();
        __syncthreads();
        const uint32_t KVB = sb + KVB0 + (uint32_t)(kb & 1) * KVSZ;

        float s[2][8][4];
#pragma unroll
        for (int mt = 0; mt < 2; mt++)
#pragma unroll
            for (int j = 0; j < 8; j++)
#pragma unroll
                for (int q = 0; q < 4; q++) s[mt][j][q] = 0.f;

        // S = Q @ K^T
#pragma unroll
        for (int kf = 0; kf < 4; kf++) {
            uint32_t qf[2][4], kfr[4][4];
#pragma unroll
            for (int mt = 0; mt < 2; mt++)
                ldsm4(qf[mt], sb + QO + (uint32_t)(wid * 32 + mt * 16 + lr) * R +
                                  (uint32_t)(kf * 16 + ac8) * 2);
#pragma unroll
            for (int nb = 0; nb < 4; nb++)
                ldsm4(kfr[nb], KVB + (uint32_t)(nb * 16 + bn) * R +
                                   (uint32_t)(kf * 16 + bc8) * 2);
#pragma unroll
            for (int mt = 0; mt < 2; mt++)
#pragma unroll
                for (int nb = 0; nb < 4; nb++) {
                    mma_f16(s[mt][2 * nb], qf[mt], &kfr[nb][0]);
                    mma_f16(s[mt][2 * nb + 1], qf[mt], &kfr[nb][2]);
                }
        }

        // online softmax per m-tile
#pragma unroll
        for (int mt = 0; mt < 2; mt++) {
            float mx0 = -INFINITY, mx1 = -INFINITY;
#pragma unroll
            for (int j = 0; j < 8; j++) {
                mx0 = fmaxf(mx0, fmaxf(s[mt][j][0], s[mt][j][1]));
                mx1 = fmaxf(mx1, fmaxf(s[mt][j][2], s[mt][j][3]));
            }
            mx0 = fmaxf(mx0, __shfl_xor_sync(0xffffffffu, mx0, 1));
            mx0 = fmaxf(mx0, __shfl_xor_sync(0xffffffffu, mx0, 2));
            mx1 = fmaxf(mx1, __shfl_xor_sync(0xffffffffu, mx1, 1));
            mx1 = fmaxf(mx1, __shfl_xor_sync(0xffffffffu, mx1, 2));
            float m0n = fmaxf(m[mt][0], mx0), m1n = fmaxf(m[mt][1], mx1);
            float sc0 = __expf((m[mt][0] - m0n) * 0.125f);
            float sc1 = __expf((m[mt][1] - m1n) * 0.125f);
            m[mt][0] = m0n;
            m[mt][1] = m1n;
            float su0 = 0.f, su1 = 0.f;
#pragma unroll
            for (int j = 0; j < 8; j++) {
                s[mt][j][0] = __expf((s[mt][j][0] - m0n) * 0.125f);
                s[mt][j][1] = __expf((s[mt][j][1] - m0n) * 0.125f);
                s[mt][j][2] = __expf((s[mt][j][2] - m1n) * 0.125f);
                s[mt][j][3] = __expf((s[mt][j][3] - m1n) * 0.125f);
                su0 += s[mt][j][0] + s[mt][j][1];
                su1 += s[mt][j][2] + s[mt][j][3];
            }
            su0 += __shfl_xor_sync(0xffffffffu, su0, 1);
            su0 += __shfl_xor_sync(0xffffffffu, su0, 2);
            su1 += __shfl_xor_sync(0xffffffffu, su1, 1);
            su1 += __shfl_xor_sync(0xffffffffu, su1, 2);
            l[mt][0] = l[mt][0] * sc0 + su0;
            l[mt][1] = l[mt][1] * sc1 + su1;
#pragma unroll
            for (int j = 0; j < 8; j++) {
                o[mt][j][0] *= sc0;
                o[mt][j][1] *= sc0;
                o[mt][j][2] *= sc1;
                o[mt][j][3] *= sc1;
            }
        }

        // O += P @ V
#pragma unroll
        for (int kf = 0; kf < 4; kf++) {
            uint32_t ph[2][4], vf[4][4];
#pragma unroll
            for (int mt = 0; mt < 2; mt++) {
                ph[mt][0] = packh2(s[mt][2 * kf][0], s[mt][2 * kf][1]);
                ph[mt][1] = packh2(s[mt][2 * kf][2], s[mt][2 * kf][3]);
                ph[mt][2] = packh2(s[mt][2 * kf + 1][0], s[mt][2 * kf + 1][1]);
                ph[mt][3] = packh2(s[mt][2 * kf + 1][2], s[mt][2 * kf + 1][3]);
            }
#pragma unroll
            for (int nb = 0; nb < 4; nb++)
                ldsm4t(vf[nb], KVB + 9216 + (uint32_t)(kf * 16 + lr) * R +
                                   (uint32_t)(nb * 16 + ac8) * 2);
#pragma unroll
            for (int mt = 0; mt < 2; mt++)
#pragma unroll
                for (int nb = 0; nb < 4; nb++) {
                    mma_f16(o[mt][2 * nb], ph[mt], &vf[nb][0]);
                    mma_f16(o[mt][2 * nb + 1], ph[mt], &vf[nb][2]);
                }
        }
        __syncthreads();
        if (kb + 2 < NKB) issueKV(kb + 2, kb & 1);
    }

    // epilogue
    const int g = lane >> 2, q = lane & 3;
#pragma unroll
    for (int mt = 0; mt < 2; mt++) {
        float i0 = 1.f / l[mt][0], i1 = 1.f / l[mt][1];
        size_t base = (size_t)(qb * 128 + wid * 32 + mt * 16) * DD + h * HD;
#pragma unroll
        for (int nj = 0; nj < 8; nj++) {
            int col = nj * 8 + q * 2;
            *(uint32_t*)(O + base + (size_t)g * DD + col) =
                packh2(o[mt][nj][0] * i0, o[mt][nj][1] * i0);
            *(uint32_t*)(O + base + (size_t)(g + 8) * DD + col) =
                packh2(o[mt][nj][2] * i1, o[mt][nj][3] * i1);
        }
    }
}

// ---------------- launch -----------------------------------------------------
extern "C" void kernel_launch(void* const* d_in, const int* in_sizes, int n_in,
                              void* d_out, int out_size) {
    const float* x     = (const float*)d_in[0];
    const float* ctx   = (const float*)d_in[1];
    const float* wq    = (const float*)d_in[2];
    const float* bq    = (const float*)d_in[3];
    const float* wk    = (const float*)d_in[4];
    const float* bk    = (const float*)d_in[5];
    const float* wv    = (const float*)d_in[6];
    const float* bv    = (const float*)d_in[7];
    const float* wo    = (const float*)d_in[8];
    const float* bo    = (const float*)d_in[9];
    const float* w1    = (const float*)d_in[10];
    const float* b1    = (const float*)d_in[11];
    const float* w2    = (const float*)d_in[12];
    const float* b2    = (const float*)d_in[13];
    const float* qn_w  = (const float*)d_in[14];
    const float* qn_b  = (const float*)d_in[15];
    const float* kvn_w = (const float*)d_in[16];
    const float* kvn_b = (const float*)d_in[17];
    const float* pn_w  = (const float*)d_in[18];
    const float* pn_b  = (const float*)d_in[19];
    float* out = (float*)d_out;

#define GETP(name) \
    ushortx* name##p; cudaGetSymbolAddress((void**)&name##p, g_##name)
    GETP(xq); GETP(kv); GETP(q); GETP(k); GETP(v); GETP(o); GETP(hln); GETP(h1);
    GETP(wq); GETP(wk); GETP(wv); GETP(wo); GETP(w1); GETP(w2);
#undef GETP
    float* x1;
    cudaGetSymbolAddress((void**)&x1, g_x1);

    const int GSM = 4 * 18944;          // 75776
    const int FSM = 18432 + 2 * 18432;  // 55296
    cudaFuncSetAttribute((const void*)qkv_gemm,
                         cudaFuncAttributeMaxDynamicSharedMemorySize, GSM);
    cudaFuncSetAttribute((const void*)half_gemm<1, 1, 0, 0>,
                         cudaFuncAttributeMaxDynamicSharedMemorySize, GSM);
    cudaFuncSetAttribute((const void*)half_gemm<1, 0, 1, 1>,
                         cudaFuncAttributeMaxDynamicSharedMemorySize, GSM);
    cudaFuncSetAttribute((const void*)flash_kernel,
                         cudaFuncAttributeMaxDynamicSharedMemorySize, FSM);

    // 0. convert weights to fp16
    convert_kernel<<<(DD * DD / 4 + 255) / 256, 256>>>(wq, wqp, DD * DD / 4);
    convert_kernel<<<(CC * DD / 4 + 255) / 256, 256>>>(wk, wkp, CC * DD / 4);
    convert_kernel<<<(CC * DD / 4 + 255) / 256, 256>>>(wv, wvp, CC * DD / 4);
    convert_kernel<<<(DD * DD / 4 + 255) / 256, 256>>>(wo, wop, DD * DD / 4);
    convert_kernel<<<(DD * FF / 4 + 255) / 256, 256>>>(w1, w1p, DD * FF / 4);
    convert_kernel<<<(FF * DD / 4 + 255) / 256, 256>>>(w2, w2p, FF * DD / 4);

    // 1. pre-norms -> fp16
    ln_half_kernel<DD><<<NT, 256>>>(x, qn_w, qn_b, xqp);
    ln_half_kernel<CC><<<MT, 256>>>(ctx, kvn_w, kvn_b, kvp);

    // 2. fused Q/K/V projections
    qkv_gemm<<<dim3(DD / 128, NT / 128, 3), 128, GSM>>>(
        xqp, kvp, wqp, wkp, wvp, bq, bk, bv, qp, kp, vp);

    // 3. fused attention (128-query tiles)
    flash_kernel<<<dim3(NT / 128, NH), 128, FSM>>>(qp, kp, vp, op);

    // 4. x1 = o @ wo + bo + x
    half_gemm<1, 1, 0, 0><<<dim3(DD / 128, NT / 128), 128, GSM>>>(
        op, wop, bo, x, x1, nullptr, DD, DD, DD);

    // 5. MLP
    ln_half_kernel<DD><<<NT, 256>>>(x1, pn_w, pn_b, hlnp);
    half_gemm<1, 0, 1, 1><<<dim3(FF / 128, NT / 128), 128, GSM>>>(
        hlnp, w1p, b1, nullptr, nullptr, h1p, DD, DD, FF);
    half_gemm<1, 1, 0, 0><<<dim3(DD / 128, NT / 128), 128, GSM>>>(
        h1p, w2p, b2, x1, out, nullptr, FF, FF, DD);
}

// round 12
// speedup vs baseline: 3.4083x; 1.1456x over previous
#include <cuda_runtime.h>
#include <cuda_fp16.h>
#include <math.h>
#include <stdint.h>

#define NT 2048
#define DD 1024
#define CC 768
#define NH 16
#define HD 64
#define MT 2048
#define FF 4096

typedef unsigned short ushortx;

// ---------------- scratch (fp16 stored as ushort) -----------------------------
__device__ ushortx g_xq[NT * DD];
__device__ ushortx g_kv[MT * CC];
__device__ ushortx g_q[NT * DD];
__device__ ushortx g_k[MT * DD];
__device__ ushortx g_v[MT * DD];
__device__ ushortx g_o[NT * DD];
__device__ float   g_x1[NT * DD];
__device__ ushortx g_hln[NT * DD];
__device__ ushortx g_h1[(size_t)NT * FF];
__device__ ushortx g_wq[DD * DD];
__device__ ushortx g_wk[CC * DD];
__device__ ushortx g_wv[CC * DD];
__device__ ushortx g_wo[DD * DD];
__device__ ushortx g_w1[(size_t)DD * FF];
__device__ ushortx g_w2[(size_t)FF * DD];

// ---------------- helpers ----------------------------------------------------
__device__ __forceinline__ uint32_t smem_addr_u32(const void* p) {
    uint32_t a;
    asm("{ .reg .u64 t; cvta.to.shared.u64 t, %1; cvt.u32.u64 %0, t; }" : "=r"(a) : "l"(p));
    return a;
}
__device__ __forceinline__ void ldsm4(uint32_t* r, uint32_t addr) {
    asm volatile("ldmatrix.sync.aligned.m8n8.x4.shared.b16 {%0,%1,%2,%3}, [%4];"
                 : "=r"(r[0]), "=r"(r[1]), "=r"(r[2]), "=r"(r[3]) : "r"(addr));
}
__device__ __forceinline__ void ldsm4t(uint32_t* r, uint32_t addr) {
    asm volatile("ldmatrix.sync.aligned.m8n8.x4.trans.shared.b16 {%0,%1,%2,%3}, [%4];"
                 : "=r"(r[0]), "=r"(r[1]), "=r"(r[2]), "=r"(r[3]) : "r"(addr));
}
__device__ __forceinline__ void mma_f16(float* d, const uint32_t* a, const uint32_t* b) {
    asm volatile(
        "mma.sync.aligned.m16n8k16.row.col.f32.f16.f16.f32 "
        "{%0,%1,%2,%3}, {%4,%5,%6,%7}, {%8,%9}, {%0,%1,%2,%3};"
        : "+f"(d[0]), "+f"(d[1]), "+f"(d[2]), "+f"(d[3])
        : "r"(a[0]), "r"(a[1]), "r"(a[2]), "r"(a[3]), "r"(b[0]), "r"(b[1]));
}
__device__ __forceinline__ uint32_t packh2(float x, float y) {
    __half2 h = __floats2half2_rn(x, y);
    return *(uint32_t*)&h;
}
__device__ __forceinline__ void cpa16(uint32_t d, const void* g) {
    asm volatile("cp.async.cg.shared.global [%0], [%1], 16;" :: "r"(d), "l"(g));
}
__device__ __forceinline__ void cpcommit() { asm volatile("cp.async.commit_group;" ::: "memory"); }
template <int N>
__device__ __forceinline__ void cpwait() {
    asm volatile("cp.async.wait_group %0;" :: "n"(N) : "memory");
}

// ---------------- convert fp32 -> fp16 ----------------------------------------
__global__ __launch_bounds__(256) void convert_kernel(
    const float* __restrict__ s, ushortx* __restrict__ h, int n4) {
    int i = blockIdx.x * 256 + threadIdx.x;
    if (i >= n4) return;
    float4 f = ((const float4*)s)[i];
    ((uint2*)h)[i] = make_uint2(packh2(f.x, f.y), packh2(f.z, f.w));
}

// ---------------- layernorm -> fp16 -------------------------------------------
__device__ __forceinline__ float block_reduce_sum(float v) {
    __shared__ float sh[8];
    int tid = threadIdx.x;
#pragma unroll
    for (int o = 16; o > 0; o >>= 1) v += __shfl_down_sync(0xffffffffu, v, o);
    if ((tid & 31) == 0) sh[tid >> 5] = v;
    __syncthreads();
    if (tid < 32) {
        v = (tid < 8) ? sh[tid] : 0.f;
#pragma unroll
        for (int o = 4; o > 0; o >>= 1) v += __shfl_down_sync(0xffffffffu, v, o);
        if (tid == 0) sh[0] = v;
    }
    __syncthreads();
    float r = sh[0];
    __syncthreads();
    return r;
}

template <int DIM>
__global__ __launch_bounds__(256) void ln_half_kernel(
    const float* __restrict__ x, const float* __restrict__ w, const float* __restrict__ b,
    ushortx* __restrict__ oh) {
    const float* xr = x + (size_t)blockIdx.x * DIM;
    int tid = threadIdx.x;
    float4 f = make_float4(0.f, 0.f, 0.f, 0.f);
    if (tid < DIM / 4) f = ((const float4*)xr)[tid];
    float s = f.x + f.y + f.z + f.w;
    float mean = block_reduce_sum(s) * (1.f / DIM);
    float vv = 0.f;
    if (tid < DIM / 4) {
        float c0 = f.x - mean, c1 = f.y - mean, c2 = f.z - mean, c3 = f.w - mean;
        vv = c0 * c0 + c1 * c1 + c2 * c2 + c3 * c3;
    }
    float var = block_reduce_sum(vv) * (1.f / DIM);
    float inv = rsqrtf(var + 1e-12f);
    if (tid < DIM / 4) {
        float4 w4 = ((const float4*)w)[tid];
        float4 b4 = ((const float4*)b)[tid];
        float o0 = (f.x - mean) * inv * w4.x + b4.x;
        float o1 = (f.y - mean) * inv * w4.y + b4.y;
        float o2 = (f.z - mean) * inv * w4.z + b4.z;
        float o3 = (f.w - mean) * inv * w4.w + b4.w;
        ((uint2*)(oh + (size_t)blockIdx.x * DIM))[tid] =
            make_uint2(packh2(o0, o1), packh2(o2, o3));
    }
}

// ---------------- fp16 GEMM core (128 thr, 4 warps, BM templated) --------------
// C[BM_ x 128] tile at (bx,by). A fp16 [M,K] lda=K; B fp16 [K,N] ldb=N.
// 4 warps in 2x2; warp tile (BM_/2) x 64.
template <int BM_, int BIAS, int RES, int GELU, int OUTH>
__device__ __forceinline__ void gemm_core(
    const ushortx* __restrict__ A, const ushortx* __restrict__ B,
    const float* __restrict__ bias, const float* __restrict__ Res,
    float* __restrict__ Cf, ushortx* __restrict__ Ch,
    int K, int lda, int ldb, int bx, int by) {
    constexpr int RA = 80, RB = 272;
    constexpr int ASZ = BM_ * RA;
    constexpr int BSZ = 32 * RB;
    constexpr int STAGE = ASZ + BSZ;
    constexpr int MI = BM_ / 32;        // m16 tiles per warp
    constexpr int ACH = BM_ * 4 / 128;  // A chunks per thread

    extern __shared__ char sm[];
    const int tid = threadIdx.x, lane = tid & 31, wid = tid >> 5;  // 4 warps
    const int wm = wid & 1, wn = wid >> 1;                         // 2x2
    const uint32_t sb = smem_addr_u32(sm);

    const ushortx* Ab = A + (size_t)by * BM_ * lda;
    const ushortx* Bb = B + (size_t)bx * 128;

    auto issue = [&](int k0, int buf) {
        uint32_t d = sb + buf * STAGE;
#pragma unroll
        for (int j = 0; j < ACH; j++) {   // A: BM_*4 chunks
            int i = tid + j * 128;
            int r = i >> 2, s = i & 3;
            cpa16(d + (uint32_t)(r * RA + s * 16), Ab + (size_t)r * lda + k0 + s * 8);
        }
#pragma unroll
        for (int j = 0; j < 4; j++) {     // B: 512 chunks
            int i = tid + j * 128;
            int kr = i >> 4, s = i & 15;
            cpa16(d + ASZ + (uint32_t)(kr * RB + s * 16),
                  Bb + (size_t)(k0 + kr) * ldb + s * 8);
        }
        cpcommit();
    };

    float acc[MI][8][4];
#pragma unroll
    for (int i = 0; i < MI; i++)
#pragma unroll
        for (int j = 0; j < 8; j++)
#pragma unroll
            for (int q = 0; q < 4; q++) acc[i][j][q] = 0.f;

    const int lr = lane & 15;
    const int ac8 = (lane >> 4) << 3;

    auto domma = [&](int buf) {
        const uint32_t ab = sb + buf * STAGE;
        const uint32_t bb = ab + ASZ;
#pragma unroll
        for (int kk = 0; kk < 2; kk++) {
            uint32_t bf[4][4];
#pragma unroll
            for (int nj = 0; nj < 4; nj++) {
                uint32_t boff = (uint32_t)(kk * 16 + lr) * RB +
                                (uint32_t)(wn * 64 + nj * 16 + ac8) * 2;
                ldsm4t(bf[nj], bb + boff);
            }
#pragma unroll
            for (int mi = 0; mi < MI; mi++) {
                uint32_t aoff = (uint32_t)(wm * (BM_ / 2) + mi * 16 + lr) * RA +
                                (uint32_t)(kk * 16 + ac8) * 2;
                uint32_t af[4];
                ldsm4(af, ab + aoff);
#pragma unroll
                for (int nj = 0; nj < 4; nj++) {
                    mma_f16(acc[mi][2 * nj], af, &bf[nj][0]);
                    mma_f16(acc[mi][2 * nj + 1], af, &bf[nj][2]);
                }
            }
        }
    };

    const int T = K >> 5;
    issue(0, 0);
    issue(32, 1);
    issue(64, 2);
#pragma unroll 1
    for (int t = 0; t < T; t++) {
        if (t + 3 <= T) cpwait<2>();
        else if (t + 2 <= T) cpwait<1>();
        else cpwait<0>();
        __syncthreads();
        if (t + 3 < T) issue((t + 3) * 32, (t + 3) & 3);
        domma(t & 3);
    }

    // epilogue
    const int g = lane >> 2, q = lane & 3;
    const size_t c0 = (size_t)by * BM_ * ldb + (size_t)bx * 128;
#pragma unroll
    for (int mi = 0; mi < MI; mi++)
#pragma unroll
        for (int nj = 0; nj < 8; nj++) {
            int col = wn * 64 + nj * 8 + q * 2;
            float bv0 = BIAS ? bias[bx * 128 + col] : 0.f;
            float bv1 = BIAS ? bias[bx * 128 + col + 1] : 0.f;
#pragma unroll
            for (int rr = 0; rr < 2; rr++) {
                int row = wm * (BM_ / 2) + mi * 16 + g + rr * 8;
                float v0 = acc[mi][nj][rr * 2] + bv0;
                float v1 = acc[mi][nj][rr * 2 + 1] + bv1;
                if (RES) {
                    const float* rp = Res + c0 + (size_t)row * ldb + col;
                    v0 += rp[0];
                    v1 += rp[1];
                }
                if (GELU) {
                    float i0 = 0.7978845608028654f * (v0 + 0.044715f * v0 * v0 * v0);
                    v0 = 0.5f * v0 * (1.f + tanhf(i0));
                    float i1 = 0.7978845608028654f * (v1 + 0.044715f * v1 * v1 * v1);
                    v1 = 0.5f * v1 * (1.f + tanhf(i1));
                }
                if (OUTH) {
                    *(uint32_t*)(Ch + c0 + (size_t)row * ldb + col) = packh2(v0, v1);
                } else {
                    *(float2*)(Cf + c0 + (size_t)row * ldb + col) = make_float2(v0, v1);
                }
            }
        }
}

template <int BM_, int BIAS, int RES, int GELU, int OUTH>
__global__ __launch_bounds__(128, 2) void half_gemm(
    const ushortx* A, const ushortx* B, const float* bias, const float* Res,
    float* Cf, ushortx* Ch, int K, int lda, int ldb) {
    gemm_core<BM_, BIAS, RES, GELU, OUTH>(A, B, bias, Res, Cf, Ch, K, lda, ldb,
                                          blockIdx.x, blockIdx.y);
}

// fused QKV
__global__ __launch_bounds__(128, 2) void qkv_gemm(
    const ushortx* xq, const ushortx* kv,
    const ushortx* wq, const ushortx* wk, const ushortx* wv,
    const float* bq, const float* bk, const float* bv,
    ushortx* q, ushortx* k, ushortx* v) {
    int z = blockIdx.z;
    const ushortx *A, *B;
    const float* bias;
    ushortx* C;
    int K, lda;
    if (z == 0) { A = xq; B = wq; bias = bq; C = q; K = DD; lda = DD; }
    else if (z == 1) { A = kv; B = wk; bias = bk; C = k; K = CC; lda = CC; }
    else { A = kv; B = wv; bias = bv; C = v; K = CC; lda = CC; }
    gemm_core<128, 1, 0, 0, 1>(A, B, bias, nullptr, nullptr, C, K, lda, DD,
                               blockIdx.x, blockIdx.y);
}

// ---------------- flash attention (128 thr, 4 warps x 32 query rows) -----------
__global__ __launch_bounds__(128, 2) void flash_kernel(
    const ushortx* __restrict__ Q, const ushortx* __restrict__ K,
    const ushortx* __restrict__ V, ushortx* __restrict__ O) {
    constexpr int R = 144;
    constexpr int QO = 0;
    constexpr int KVB0 = 18432, KVSZ = 18432;
    constexpr int NKB = MT / 64;

    extern __shared__ char sm[];
    const int tid = threadIdx.x, lane = tid & 31, wid = tid >> 5;
    const int h = blockIdx.y, qb = blockIdx.x;
    const uint32_t sb = smem_addr_u32(sm);

    const ushortx* Qg = Q + (size_t)qb * 128 * DD + h * HD;
    const ushortx* Kg = K + h * HD;
    const ushortx* Vg = V + h * HD;

#pragma unroll
    for (int j = 0; j < 8; j++) {
        int i = tid + j * 128;
        int r = i >> 3, s = i & 7;
        cpa16(sb + QO + (uint32_t)(r * R + s * 16), Qg + (size_t)r * DD + s * 8);
    }
    auto issueKV = [&](int kb, int buf) {
        uint32_t base = sb + KVB0 + (uint32_t)buf * KVSZ;
#pragma unroll
        for (int j = 0; j < 4; j++) {
            int i = tid + j * 128;
            int r = i >> 3, s = i & 7;
            uint32_t dd = base + (uint32_t)(r * R + s * 16);
            size_t so = (size_t)(kb * 64 + r) * DD + s * 8;
            cpa16(dd, Kg + so);
            cpa16(dd + 9216, Vg + so);
        }
        cpcommit();
    };
    issueKV(0, 0);
    issueKV(1, 1);

    float o[2][8][4];
#pragma unroll
    for (int mt = 0; mt < 2; mt++)
#pragma unroll
        for (int j = 0; j < 8; j++)
#pragma unroll
            for (int q = 0; q < 4; q++) o[mt][j][q] = 0.f;
    float m[2][2] = {{-INFINITY, -INFINITY}, {-INFINITY, -INFINITY}};
    float l[2][2] = {{0.f, 0.f}, {0.f, 0.f}};

    const int lr = lane & 15;
    const int ac8 = (lane >> 4) << 3;
    const int bn = (lane & 7) + ((lane >> 4) << 3);
    const int bc8 = ((lane >> 3) & 1) << 3;

    for (int kb = 0; kb < NKB; kb++) {
        if (kb < NKB - 1) cpwait<1>();
        else cpwait<0>();
        __syncthreads();
        const uint32_t KVB = sb + KVB0 + (uint32_t)(kb & 1) * KVSZ;

        float s[2][8][4];
#pragma unroll
        for (int mt = 0; mt < 2; mt++)
#pragma unroll
            for (int j = 0; j < 8; j++)
#pragma unroll
                for (int q = 0; q < 4; q++) s[mt][j][q] = 0.f;

#pragma unroll
        for (int kf = 0; kf < 4; kf++) {
            uint32_t qf[2][4], kfr[4][4];
#pragma unroll
            for (int mt = 0; mt < 2; mt++)
                ldsm4(qf[mt], sb + QO + (uint32_t)(wid * 32 + mt * 16 + lr) * R +
                                  (uint32_t)(kf * 16 + ac8) * 2);
#pragma unroll
            for (int nb = 0; nb < 4; nb++)
                ldsm4(kfr[nb], KVB + (uint32_t)(nb * 16 + bn) * R +
                                   (uint32_t)(kf * 16 + bc8) * 2);
#pragma unroll
            for (int mt = 0; mt < 2; mt++)
#pragma unroll
                for (int nb = 0; nb < 4; nb++) {
                    mma_f16(s[mt][2 * nb], qf[mt], &kfr[nb][0]);
                    mma_f16(s[mt][2 * nb + 1], qf[mt], &kfr[nb][2]);
                }
        }

#pragma unroll
        for (int mt = 0; mt < 2; mt++) {
            float mx0 = -INFINITY, mx1 = -INFINITY;
#pragma unroll
            for (int j = 0; j < 8; j++) {
                mx0 = fmaxf(mx0, fmaxf(s[mt][j][0], s[mt][j][1]));
                mx1 = fmaxf(mx1, fmaxf(s[mt][j][2], s[mt][j][3]));
            }
            mx0 = fmaxf(mx0, __shfl_xor_sync(0xffffffffu, mx0, 1));
            mx0 = fmaxf(mx0, __shfl_xor_sync(0xffffffffu, mx0, 2));
            mx1 = fmaxf(mx1, __shfl_xor_sync(0xffffffffu, mx1, 1));
            mx1 = fmaxf(mx1, __shfl_xor_sync(0xffffffffu, mx1, 2));
            float m0n = fmaxf(m[mt][0], mx0), m1n = fmaxf(m[mt][1], mx1);
            float sc0 = __expf((m[mt][0] - m0n) * 0.125f);
            float sc1 = __expf((m[mt][1] - m1n) * 0.125f);
            m[mt][0] = m0n;
            m[mt][1] = m1n;
            float su0 = 0.f, su1 = 0.f;
#pragma unroll
            for (int j = 0; j < 8; j++) {
                s[mt][j][0] = __expf((s[mt][j][0] - m0n) * 0.125f);
                s[mt][j][1] = __expf((s[mt][j][1] - m0n) * 0.125f);
                s[mt][j][2] = __expf((s[mt][j][2] - m1n) * 0.125f);
                s[mt][j][3] = __expf((s[mt][j][3] - m1n) * 0.125f);
                su0 += s[mt][j][0] + s[mt][j][1];
                su1 += s[mt][j][2] + s[mt][j][3];
            }
            su0 += __shfl_xor_sync(0xffffffffu, su0, 1);
            su0 += __shfl_xor_sync(0xffffffffu, su0, 2);
            su1 += __shfl_xor_sync(0xffffffffu, su1, 1);
            su1 += __shfl_xor_sync(0xffffffffu, su1, 2);
            l[mt][0] = l[mt][0] * sc0 + su0;
            l[mt][1] = l[mt][1] * sc1 + su1;
#pragma unroll
            for (int j = 0; j < 8; j++) {
                o[mt][j][0] *= sc0;
                o[mt][j][1] *= sc0;
                o[mt][j][2] *= sc1;
                o[mt][j][3] *= sc1;
            }
        }

#pragma unroll
        for (int kf = 0; kf < 4; kf++) {
            uint32_t ph[2][4], vf[4][4];
#pragma unroll
            for (int mt = 0; mt < 2; mt++) {
                ph[mt][0] = packh2(s[mt][2 * kf][0], s[mt][2 * kf][1]);
                ph[mt][1] = packh2(s[mt][2 * kf][2], s[mt][2 * kf][3]);
                ph[mt][2] = packh2(s[mt][2 * kf + 1][0], s[mt][2 * kf + 1][1]);
                ph[mt][3] = packh2(s[mt][2 * kf + 1][2], s[mt][2 * kf + 1][3]);
            }
#pragma unroll
            for (int nb = 0; nb < 4; nb++)
                ldsm4t(vf[nb], KVB + 9216 + (uint32_t)(kf * 16 + lr) * R +
                                   (uint32_t)(nb * 16 + ac8) * 2);
#pragma unroll
            for (int mt = 0; mt < 2; mt++)
#pragma unroll
                for (int nb = 0; nb < 4; nb++) {
                    mma_f16(o[mt][2 * nb], ph[mt], &vf[nb][0]);
                    mma_f16(o[mt][2 * nb + 1], ph[mt], &vf[nb][2]);
                }
        }
        __syncthreads();
        if (kb + 2 < NKB) issueKV(kb + 2, kb & 1);
    }

    const int g = lane >> 2, q = lane & 3;
#pragma unroll
    for (int mt = 0; mt < 2; mt++) {
        float i0 = 1.f / l[mt][0], i1 = 1.f / l[mt][1];
        size_t base = (size_t)(qb * 128 + wid * 32 + mt * 16) * DD + h * HD;
#pragma unroll
        for (int nj = 0; nj < 8; nj++) {
            int col = nj * 8 + q * 2;
            *(uint32_t*)(O + base + (size_t)g * DD + col) =
                packh2(o[mt][nj][0] * i0, o[mt][nj][1] * i0);
            *(uint32_t*)(O + base + (size_t)(g + 8) * DD + col) =
                packh2(o[mt][nj][2] * i1, o[mt][nj][3] * i1);
        }
    }
}

// ---------------- launch -----------------------------------------------------
extern "C" void kernel_launch(void* const* d_in, const int* in_sizes, int n_in,
                              void* d_out, int out_size) {
    const float* x     = (const float*)d_in[0];
    const float* ctx   = (const float*)d_in[1];
    const float* wq    = (const float*)d_in[2];
    const float* bq    = (const float*)d_in[3];
    const float* wk    = (const float*)d_in[4];
    const float* bk    = (const float*)d_in[5];
    const float* wv    = (const float*)d_in[6];
    const float* bv    = (const float*)d_in[7];
    const float* wo    = (const float*)d_in[8];
    const float* bo    = (const float*)d_in[9];
    const float* w1    = (const float*)d_in[10];
    const float* b1    = (const float*)d_in[11];
    const float* w2    = (const float*)d_in[12];
    const float* b2    = (const float*)d_in[13];
    const float* qn_w  = (const float*)d_in[14];
    const float* qn_b  = (const float*)d_in[15];
    const float* kvn_w = (const float*)d_in[16];
    const float* kvn_b = (const float*)d_in[17];
    const float* pn_w  = (const float*)d_in[18];
    const float* pn_b  = (const float*)d_in[19];
    float* out = (float*)d_out;

#define GETP(name) \
    ushortx* name##p; cudaGetSymbolAddress((void**)&name##p, g_##name)
    GETP(xq); GETP(kv); GETP(q); GETP(k); GETP(v); GETP(o); GETP(hln); GETP(h1);
    GETP(wq); GETP(wk); GETP(wv); GETP(wo); GETP(w1); GETP(w2);
#undef GETP
    float* x1;
    cudaGetSymbolAddress((void**)&x1, g_x1);

    const int GSM128 = 4 * (128 * 80 + 32 * 272);  // 75776
    const int GSM64  = 4 * (64 * 80 + 32 * 272);   // 55296
    const int FSM = 18432 + 2 * 18432;             // 55296
    cudaFuncSetAttribute((const void*)qkv_gemm,
                         cudaFuncAttributeMaxDynamicSharedMemorySize, GSM128);
    cudaFuncSetAttribute((const void*)half_gemm<64, 1, 1, 0, 0>,
                         cudaFuncAttributeMaxDynamicSharedMemorySize, GSM64);
    cudaFuncSetAttribute((const void*)half_gemm<128, 1, 0, 1, 1>,
                         cudaFuncAttributeMaxDynamicSharedMemorySize, GSM128);
    cudaFuncSetAttribute((const void*)flash_kernel,
                         cudaFuncAttributeMaxDynamicSharedMemorySize, FSM);

    // 0. convert weights to fp16
    convert_kernel<<<(DD * DD / 4 + 255) / 256, 256>>>(wq, wqp, DD * DD / 4);
    convert_kernel<<<(CC * DD / 4 + 255) / 256, 256>>>(wk, wkp, CC * DD / 4);
    convert_kernel<<<(CC * DD / 4 + 255) / 256, 256>>>(wv, wvp, CC * DD / 4);
    convert_kernel<<<(DD * DD / 4 + 255) / 256, 256>>>(wo, wop, DD * DD / 4);
    convert_kernel<<<(DD * FF / 4 + 255) / 256, 256>>>(w1, w1p, DD * FF / 4);
    convert_kernel<<<(FF * DD / 4 + 255) / 256, 256>>>(w2, w2p, FF * DD / 4);

    // 1. pre-norms -> fp16
    ln_half_kernel<DD><<<NT, 256>>>(x, qn_w, qn_b, xqp);
    ln_half_kernel<CC><<<MT, 256>>>(ctx, kvn_w, kvn_b, kvp);

    // 2. fused Q/K/V projections
    qkv_gemm<<<dim3(DD / 128, NT / 128, 3), 128, GSM128>>>(
        xqp, kvp, wqp, wkp, wvp, bq, bk, bv, qp, kp, vp);

    // 3. fused attention
    flash_kernel<<<dim3(NT / 128, NH), 128, FSM>>>(qp, kp, vp, op);

    // 4. x1 = o @ wo + bo + x   (BM=64 -> grid 8x32 = 256 CTAs)
    half_gemm<64, 1, 1, 0, 0><<<dim3(DD / 128, NT / 64), 128, GSM64>>>(
        op, wop, bo, x, x1, nullptr, DD, DD, DD);

    // 5. MLP
    ln_half_kernel<DD><<<NT, 256>>>(x1, pn_w, pn_b, hlnp);
    half_gemm<128, 1, 0, 1, 1><<<dim3(FF / 128, NT / 128), 128, GSM128>>>(
        hlnp, w1p, b1, nullptr, nullptr, h1p, DD, DD, FF);
    half_gemm<64, 1, 1, 0, 0><<<dim3(DD / 128, NT / 64), 128, GSM64>>>(
        h1p, w2p, b2, x1, out, nullptr, FF, FF, DD);
}

// round 14
// speedup vs baseline: 3.5582x; 1.0440x over previous
#include <cuda_runtime.h>
#include <cuda_fp16.h>
#include <math.h>
#include <stdint.h>

#define NT 2048
#define DD 1024
#define CC 768
#define NH 16
#define HD 64
#define MT 2048
#define FF 4096

typedef unsigned short ushortx;

// ---------------- scratch (fp16 stored as ushort) -----------------------------
__device__ ushortx g_xq[NT * DD];
__device__ ushortx g_kv[MT * CC];
__device__ ushortx g_q[NT * DD];
__device__ ushortx g_k[MT * DD];
__device__ ushortx g_v[MT * DD];
__device__ ushortx g_o[NT * DD];
__device__ float   g_x1[NT * DD];
__device__ ushortx g_hln[NT * DD];
__device__ ushortx g_h1[(size_t)NT * FF];
__device__ ushortx g_wq[DD * DD];
__device__ ushortx g_wk[CC * DD];
__device__ ushortx g_wv[CC * DD];
__device__ ushortx g_wo[DD * DD];
__device__ ushortx g_w1[(size_t)DD * FF];
__device__ ushortx g_w2[(size_t)FF * DD];

// ---------------- helpers ----------------------------------------------------
__device__ __forceinline__ uint32_t smem_addr_u32(const void* p) {
    uint32_t a;
    asm("{ .reg .u64 t; cvta.to.shared.u64 t, %1; cvt.u32.u64 %0, t; }" : "=r"(a) : "l"(p));
    return a;
}
__device__ __forceinline__ void ldsm4(uint32_t* r, uint32_t addr) {
    asm volatile("ldmatrix.sync.aligned.m8n8.x4.shared.b16 {%0,%1,%2,%3}, [%4];"
                 : "=r"(r[0]), "=r"(r[1]), "=r"(r[2]), "=r"(r[3]) : "r"(addr));
}
__device__ __forceinline__ void ldsm4t(uint32_t* r, uint32_t addr) {
    asm volatile("ldmatrix.sync.aligned.m8n8.x4.trans.shared.b16 {%0,%1,%2,%3}, [%4];"
                 : "=r"(r[0]), "=r"(r[1]), "=r"(r[2]), "=r"(r[3]) : "r"(addr));
}
__device__ __forceinline__ void mma_f16(float* d, const uint32_t* a, const uint32_t* b) {
    asm volatile(
        "mma.sync.aligned.m16n8k16.row.col.f32.f16.f16.f32 "
        "{%0,%1,%2,%3}, {%4,%5,%6,%7}, {%8,%9}, {%0,%1,%2,%3};"
        : "+f"(d[0]), "+f"(d[1]), "+f"(d[2]), "+f"(d[3])
        : "r"(a[0]), "r"(a[1]), "r"(a[2]), "r"(a[3]), "r"(b[0]), "r"(b[1]));
}
__device__ __forceinline__ uint32_t packh2(float x, float y) {
    __half2 h = __floats2half2_rn(x, y);
    return *(uint32_t*)&h;
}
__device__ __forceinline__ void cpa16(uint32_t d, const void* g) {
    asm volatile("cp.async.cg.shared.global [%0], [%1], 16;" :: "r"(d), "l"(g));
}
__device__ __forceinline__ void cpcommit() { asm volatile("cp.async.commit_group;" ::: "memory"); }
template <int N>
__device__ __forceinline__ void cpwait() {
    asm volatile("cp.async.wait_group %0;" :: "n"(N) : "memory");
}

// ---------------- block reduce -------------------------------------------------
__device__ __forceinline__ float block_reduce_sum(float v) {
    __shared__ float sh[8];
    int tid = threadIdx.x;
#pragma unroll
    for (int o = 16; o > 0; o >>= 1) v += __shfl_down_sync(0xffffffffu, v, o);
    if ((tid & 31) == 0) sh[tid >> 5] = v;
    __syncthreads();
    if (tid < 32) {
        v = (tid < 8) ? sh[tid] : 0.f;
#pragma unroll
        for (int o = 4; o > 0; o >>= 1) v += __shfl_down_sync(0xffffffffu, v, o);
        if (tid == 0) sh[0] = v;
    }
    __syncthreads();
    float r = sh[0];
    __syncthreads();
    return r;
}

// ---------------- LN row body (256 threads) ------------------------------------
template <int DIM>
__device__ __forceinline__ void ln_body(
    const float* __restrict__ xr, const float* __restrict__ w,
    const float* __restrict__ b, ushortx* __restrict__ orow) {
    int tid = threadIdx.x;
    float4 f = make_float4(0.f, 0.f, 0.f, 0.f);
    if (tid < DIM / 4) f = ((const float4*)xr)[tid];
    float s = f.x + f.y + f.z + f.w;
    float mean = block_reduce_sum(s) * (1.f / DIM);
    float vv = 0.f;
    if (tid < DIM / 4) {
        float c0 = f.x - mean, c1 = f.y - mean, c2 = f.z - mean, c3 = f.w - mean;
        vv = c0 * c0 + c1 * c1 + c2 * c2 + c3 * c3;
    }
    float var = block_reduce_sum(vv) * (1.f / DIM);
    float inv = rsqrtf(var + 1e-12f);
    if (tid < DIM / 4) {
        float4 w4 = ((const float4*)w)[tid];
        float4 b4 = ((const float4*)b)[tid];
        float o0 = (f.x - mean) * inv * w4.x + b4.x;
        float o1 = (f.y - mean) * inv * w4.y + b4.y;
        float o2 = (f.z - mean) * inv * w4.z + b4.z;
        float o3 = (f.w - mean) * inv * w4.w + b4.w;
        ((uint2*)orow)[tid] = make_uint2(packh2(o0, o1), packh2(o2, o3));
    }
}

template <int DIM>
__global__ __launch_bounds__(256) void ln_half_kernel(
    const float* __restrict__ x, const float* __restrict__ w, const float* __restrict__ b,
    ushortx* __restrict__ oh) {
    ln_body<DIM>(x + (size_t)blockIdx.x * DIM, w, b, oh + (size_t)blockIdx.x * DIM);
}

// ---------------- fused prologue: 2 LNs + 6 weight converts --------------------
// blocks [0,2048): LN(x); [2048,4096): LN(ctx); rest: flat float4 convert.
#define CV_WQ (DD * DD / 4)          // 262144
#define CV_WK (CC * DD / 4)          // 196608
#define CV_TOT (2 * CV_WQ + 2 * CV_WK + 2 * (DD * FF / 4))  // 3014656
#define CV_BLOCKS ((CV_TOT + 255) / 256)                    // 11776

__global__ __launch_bounds__(256) void prologue_kernel(
    const float* __restrict__ x, const float* __restrict__ qn_w,
    const float* __restrict__ qn_b, ushortx* __restrict__ xq,
    const float* __restrict__ ctx, const float* __restrict__ kvn_w,
    const float* __restrict__ kvn_b, ushortx* __restrict__ kv,
    const float* __restrict__ wq, ushortx* __restrict__ wqp,
    const float* __restrict__ wk, ushortx* __restrict__ wkp,
    const float* __restrict__ wv, ushortx* __restrict__ wvp,
    const float* __restrict__ wo, ushortx* __restrict__ wop,
    const float* __restrict__ w1, ushortx* __restrict__ w1p,
    const float* __restrict__ w2, ushortx* __restrict__ w2p) {
    int b = blockIdx.x;
    if (b < NT) {
        ln_body<DD>(x + (size_t)b * DD, qn_w, qn_b, xq + (size_t)b * DD);
        return;
    }
    if (b < NT + MT) {
        int r = b - NT;
        ln_body<CC>(ctx + (size_t)r * CC, kvn_w, kvn_b, kv + (size_t)r * CC);
        return;
    }
    int i = (b - NT - MT) * 256 + threadIdx.x;
    if (i >= CV_TOT) return;
    const float* s;
    ushortx* d;
    if (i < CV_WQ) { s = wq; d = wqp; }
    else if (i < CV_WQ + CV_WK) { s = wk; d = wkp; i -= CV_WQ; }
    else if (i < CV_WQ + 2 * CV_WK) { s = wv; d = wvp; i -= CV_WQ + CV_WK; }
    else if (i < 2 * CV_WQ + 2 * CV_WK) { s = wo; d = wop; i -= CV_WQ + 2 * CV_WK; }
    else if (i < 2 * CV_WQ + 2 * CV_WK + DD * FF / 4) {
        s = w1; d = w1p; i -= 2 * CV_WQ + 2 * CV_WK;
    } else { s = w2; d = w2p; i -= 2 * CV_WQ + 2 * CV_WK + DD * FF / 4; }
    float4 f = ((const float4*)s)[i];
    ((uint2*)d)[i] = make_uint2(packh2(f.x, f.y), packh2(f.z, f.w));
}

// ---------------- fp16 GEMM core (128 thr, 4 warps, BM templated) --------------
template <int BM_, int BIAS, int RES, int GELU, int OUTH>
__device__ __forceinline__ void gemm_core(
    const ushortx* __restrict__ A, const ushortx* __restrict__ B,
    const float* __restrict__ bias, const float* __restrict__ Res,
    float* __restrict__ Cf, ushortx* __restrict__ Ch,
    int K, int lda, int ldb, int bx, int by) {
    constexpr int RA = 80, RB = 272;
    constexpr int ASZ = BM_ * RA;
    constexpr int BSZ = 32 * RB;
    constexpr int STAGE = ASZ + BSZ;
    constexpr int MI = BM_ / 32;
    constexpr int ACH = BM_ * 4 / 128;

    extern __shared__ char sm[];
    const int tid = threadIdx.x, lane = tid & 31, wid = tid >> 5;
    const int wm = wid & 1, wn = wid >> 1;
    const uint32_t sb = smem_addr_u32(sm);

    const ushortx* Ab = A + (size_t)by * BM_ * lda;
    const ushortx* Bb = B + (size_t)bx * 128;

    auto issue = [&](int k0, int buf) {
        uint32_t d = sb + buf * STAGE;
#pragma unroll
        for (int j = 0; j < ACH; j++) {
            int i = tid + j * 128;
            int r = i >> 2, s = i & 3;
            cpa16(d + (uint32_t)(r * RA + s * 16), Ab + (size_t)r * lda + k0 + s * 8);
        }
#pragma unroll
        for (int j = 0; j < 4; j++) {
            int i = tid + j * 128;
            int kr = i >> 4, s = i & 15;
            cpa16(d + ASZ + (uint32_t)(kr * RB + s * 16),
                  Bb + (size_t)(k0 + kr) * ldb + s * 8);
        }
        cpcommit();
    };

    float acc[MI][8][4];
#pragma unroll
    for (int i = 0; i < MI; i++)
#pragma unroll
        for (int j = 0; j < 8; j++)
#pragma unroll
            for (int q = 0; q < 4; q++) acc[i][j][q] = 0.f;

    const int lr = lane & 15;
    const int ac8 = (lane >> 4) << 3;

    auto domma = [&](int buf) {
        const uint32_t ab = sb + buf * STAGE;
        const uint32_t bb = ab + ASZ;
#pragma unroll
        for (int kk = 0; kk < 2; kk++) {
            uint32_t bf[4][4];
#pragma unroll
            for (int nj = 0; nj < 4; nj++) {
                uint32_t boff = (uint32_t)(kk * 16 + lr) * RB +
                                (uint32_t)(wn * 64 + nj * 16 + ac8) * 2;
                ldsm4t(bf[nj], bb + boff);
            }
#pragma unroll
            for (int mi = 0; mi < MI; mi++) {
                uint32_t aoff = (uint32_t)(wm * (BM_ / 2) + mi * 16 + lr) * RA +
                                (uint32_t)(kk * 16 + ac8) * 2;
                uint32_t af[4];
                ldsm4(af, ab + aoff);
#pragma unroll
                for (int nj = 0; nj < 4; nj++) {
                    mma_f16(acc[mi][2 * nj], af, &bf[nj][0]);
                    mma_f16(acc[mi][2 * nj + 1], af, &bf[nj][2]);
                }
            }
        }
    };

    const int T = K >> 5;
    issue(0, 0);
    issue(32, 1);
    issue(64, 2);
#pragma unroll 1
    for (int t = 0; t < T; t++) {
        if (t + 3 <= T) cpwait<2>();
        else if (t + 2 <= T) cpwait<1>();
        else cpwait<0>();
        __syncthreads();
        if (t + 3 < T) issue((t + 3) * 32, (t + 3) & 3);
        domma(t & 3);
    }

    // epilogue
    const int g = lane >> 2, q = lane & 3;
    const size_t c0 = (size_t)by * BM_ * ldb + (size_t)bx * 128;
#pragma unroll
    for (int mi = 0; mi < MI; mi++)
#pragma unroll
        for (int nj = 0; nj < 8; nj++) {
            int col = wn * 64 + nj * 8 + q * 2;
            float bv0 = BIAS ? bias[bx * 128 + col] : 0.f;
            float bv1 = BIAS ? bias[bx * 128 + col + 1] : 0.f;
#pragma unroll
            for (int rr = 0; rr < 2; rr++) {
                int row = wm * (BM_ / 2) + mi * 16 + g + rr * 8;
                float v0 = acc[mi][nj][rr * 2] + bv0;
                float v1 = acc[mi][nj][rr * 2 + 1] + bv1;
                if (RES) {
                    const float* rp = Res + c0 + (size_t)row * ldb + col;
                    v0 += rp[0];
                    v1 += rp[1];
                }
                if (GELU) {
                    float i0 = 0.7978845608028654f * (v0 + 0.044715f * v0 * v0 * v0);
                    v0 = 0.5f * v0 * (1.f + tanhf(i0));
                    float i1 = 0.7978845608028654f * (v1 + 0.044715f * v1 * v1 * v1);
                    v1 = 0.5f * v1 * (1.f + tanhf(i1));
                }
                if (OUTH) {
                    *(uint32_t*)(Ch + c0 + (size_t)row * ldb + col) = packh2(v0, v1);
                } else {
                    *(float2*)(Cf + c0 + (size_t)row * ldb + col) = make_float2(v0, v1);
                }
            }
        }
}

template <int BM_, int BIAS, int RES, int GELU, int OUTH>
__global__ __launch_bounds__(128, 2) void half_gemm(
    const ushortx* A, const ushortx* B, const float* bias, const float* Res,
    float* Cf, ushortx* Ch, int K, int lda, int ldb) {
    gemm_core<BM_, BIAS, RES, GELU, OUTH>(A, B, bias, Res, Cf, Ch, K, lda, ldb,
                                          blockIdx.x, blockIdx.y);
}

// fused QKV
__global__ __launch_bounds__(128, 2) void qkv_gemm(
    const ushortx* xq, const ushortx* kv,
    const ushortx* wq, const ushortx* wk, const ushortx* wv,
    const float* bq, const float* bk, const float* bv,
    ushortx* q, ushortx* k, ushortx* v) {
    int z = blockIdx.z;
    const ushortx *A, *B;
    const float* bias;
    ushortx* C;
    int K, lda;
    if (z == 0) { A = xq; B = wq; bias = bq; C = q; K = DD; lda = DD; }
    else if (z == 1) { A = kv; B = wk; bias = bk; C = k; K = CC; lda = CC; }
    else { A = kv; B = wv; bias = bv; C = v; K = CC; lda = CC; }
    gemm_core<128, 1, 0, 0, 1>(A, B, bias, nullptr, nullptr, C, K, lda, DD,
                               blockIdx.x, blockIdx.y);
}

// ---------------- flash attention (128 thr, 4 warps x 32 query rows) -----------
__global__ __launch_bounds__(128, 2) void flash_kernel(
    const ushortx* __restrict__ Q, const ushortx* __restrict__ K,
    const ushortx* __restrict__ V, ushortx* __restrict__ O) {
    constexpr int R = 144;
    constexpr int QO = 0;
    constexpr int KVB0 = 18432, KVSZ = 18432;
    constexpr int NKB = MT / 64;

    extern __shared__ char sm[];
    const int tid = threadIdx.x, lane = tid & 31, wid = tid >> 5;
    const int h = blockIdx.y, qb = blockIdx.x;
    const uint32_t sb = smem_addr_u32(sm);

    const ushortx* Qg = Q + (size_t)qb * 128 * DD + h * HD;
    const ushortx* Kg = K + h * HD;
    const ushortx* Vg = V + h * HD;

#pragma unroll
    for (int j = 0; j < 8; j++) {
        int i = tid + j * 128;
        int r = i >> 3, s = i & 7;
        cpa16(sb + QO + (uint32_t)(r * R + s * 16), Qg + (size_t)r * DD + s * 8);
    }
    auto issueKV = [&](int kb, int buf) {
        uint32_t base = sb + KVB0 + (uint32_t)buf * KVSZ;
#pragma unroll
        for (int j = 0; j < 4; j++) {
            int i = tid + j * 128;
            int r = i >> 3, s = i & 7;
            uint32_t dd = base + (uint32_t)(r * R + s * 16);
            size_t so = (size_t)(kb * 64 + r) * DD + s * 8;
            cpa16(dd, Kg + so);
            cpa16(dd + 9216, Vg + so);
        }
        cpcommit();
    };
    issueKV(0, 0);
    issueKV(1, 1);

    float o[2][8][4];
#pragma unroll
    for (int mt = 0; mt < 2; mt++)
#pragma unroll
        for (int j = 0; j < 8; j++)
#pragma unroll
            for (int q = 0; q < 4; q++) o[mt][j][q] = 0.f;
    float m[2][2] = {{-INFINITY, -INFINITY}, {-INFINITY, -INFINITY}};
    float l[2][2] = {{0.f, 0.f}, {0.f, 0.f}};

    const int lr = lane & 15;
    const int ac8 = (lane >> 4) << 3;
    const int bn = (lane & 7) + ((lane >> 4) << 3);
    const int bc8 = ((lane >> 3) & 1) << 3;

    for (int kb = 0; kb < NKB; kb++) {
        if (kb < NKB - 1) cpwait<1>();
        else cpwait<0>();
        __syncthreads();
        const uint32_t KVB = sb + KVB0 + (uint32_t)(kb & 1) * KVSZ;

        float s[2][8][4];
#pragma unroll
        for (int mt = 0; mt < 2; mt++)
#pragma unroll
            for (int j = 0; j < 8; j++)
#pragma unroll
                for (int q = 0; q < 4; q++) s[mt][j][q] = 0.f;

#pragma unroll
        for (int kf = 0; kf < 4; kf++) {
            uint32_t qf[2][4], kfr[4][4];
#pragma unroll
            for (int mt = 0; mt < 2; mt++)
                ldsm4(qf[mt], sb + QO + (uint32_t)(wid * 32 + mt * 16 + lr) * R +
                                  (uint32_t)(kf * 16 + ac8) * 2);
#pragma unroll
            for (int nb = 0; nb < 4; nb++)
                ldsm4(kfr[nb], KVB + (uint32_t)(nb * 16 + bn) * R +
                                   (uint32_t)(kf * 16 + bc8) * 2);
#pragma unroll
            for (int mt = 0; mt < 2; mt++)
#pragma unroll
                for (int nb = 0; nb < 4; nb++) {
                    mma_f16(s[mt][2 * nb], qf[mt], &kfr[nb][0]);
                    mma_f16(s[mt][2 * nb + 1], qf[mt], &kfr[nb][2]);
                }
        }

#pragma unroll
        for (int mt = 0; mt < 2; mt++) {
            float mx0 = -INFINITY, mx1 = -INFINITY;
#pragma unroll
            for (int j = 0; j < 8; j++) {
                mx0 = fmaxf(mx0, fmaxf(s[mt][j][0], s[mt][j][1]));
                mx1 = fmaxf(mx1, fmaxf(s[mt][j][2], s[mt][j][3]));
            }
            mx0 = fmaxf(mx0, __shfl_xor_sync(0xffffffffu, mx0, 1));
            mx0 = fmaxf(mx0, __shfl_xor_sync(0xffffffffu, mx0, 2));
            mx1 = fmaxf(mx1, __shfl_xor_sync(0xffffffffu, mx1, 1));
            mx1 = fmaxf(mx1, __shfl_xor_sync(0xffffffffu, mx1, 2));
            float m0n = fmaxf(m[mt][0], mx0), m1n = fmaxf(m[mt][1], mx1);
            float sc0 = __expf((m[mt][0] - m0n) * 0.125f);
            float sc1 = __expf((m[mt][1] - m1n) * 0.125f);
            m[mt][0] = m0n;
            m[mt][1] = m1n;
            float su0 = 0.f, su1 = 0.f;
#pragma unroll
            for (int j = 0; j < 8; j++) {
                s[mt][j][0] = __expf((s[mt][j][0] - m0n) * 0.125f);
                s[mt][j][1] = __expf((s[mt][j][1] - m0n) * 0.125f);
                s[mt][j][2] = __expf((s[mt][j][2] - m1n) * 0.125f);
                s[mt][j][3] = __expf((s[mt][j][3] - m1n) * 0.125f);
                su0 += s[mt][j][0] + s[mt][j][1];
                su1 += s[mt][j][2] + s[mt][j][3];
            }
            su0 += __shfl_xor_sync(0xffffffffu, su0, 1);
            su0 += __shfl_xor_sync(0xffffffffu, su0, 2);
            su1 += __shfl_xor_sync(0xffffffffu, su1, 1);
            su1 += __shfl_xor_sync(0xffffffffu, su1, 2);
            l[mt][0] = l[mt][0] * sc0 + su0;
            l[mt][1] = l[mt][1] * sc1 + su1;
#pragma unroll
            for (int j = 0; j < 8; j++) {
                o[mt][j][0] *= sc0;
                o[mt][j][1] *= sc0;
                o[mt][j][2] *= sc1;
                o[mt][j][3] *= sc1;
            }
        }

#pragma unroll
        for (int kf = 0; kf < 4; kf++) {
            uint32_t ph[2][4], vf[4][4];
#pragma unroll
            for (int mt = 0; mt < 2; mt++) {
                ph[mt][0] = packh2(s[mt][2 * kf][0], s[mt][2 * kf][1]);
                ph[mt][1] = packh2(s[mt][2 * kf][2], s[mt][2 * kf][3]);
                ph[mt][2] = packh2(s[mt][2 * kf + 1][0], s[mt][2 * kf + 1][1]);
                ph[mt][3] = packh2(s[mt][2 * kf + 1][2], s[mt][2 * kf + 1][3]);
            }
#pragma unroll
            for (int nb = 0; nb < 4; nb++)
                ldsm4t(vf[nb], KVB + 9216 + (uint32_t)(kf * 16 + lr) * R +
                                   (uint32_t)(nb * 16 + ac8) * 2);
#pragma unroll
            for (int mt = 0; mt < 2; mt++)
#pragma unroll
                for (int nb = 0; nb < 4; nb++) {
                    mma_f16(o[mt][2 * nb], ph[mt], &vf[nb][0]);
                    mma_f16(o[mt][2 * nb + 1], ph[mt], &vf[nb][2]);
                }
        }
        __syncthreads();
        if (kb + 2 < NKB) issueKV(kb + 2, kb & 1);
    }

    const int g = lane >> 2, q = lane & 3;
#pragma unroll
    for (int mt = 0; mt < 2; mt++) {
        float i0 = 1.f / l[mt][0], i1 = 1.f / l[mt][1];
        size_t base = (size_t)(qb * 128 + wid * 32 + mt * 16) * DD + h * HD;
#pragma unroll
        for (int nj = 0; nj < 8; nj++) {
            int col = nj * 8 + q * 2;
            *(uint32_t*)(O + base + (size_t)g * DD + col) =
                packh2(o[mt][nj][0] * i0, o[mt][nj][1] * i0);
            *(uint32_t*)(O + base + (size_t)(g + 8) * DD + col) =
                packh2(o[mt][nj][2] * i1, o[mt][nj][3] * i1);
        }
    }
}

// ---------------- launch -----------------------------------------------------
extern "C" void kernel_launch(void* const* d_in, const int* in_sizes, int n_in,
                              void* d_out, int out_size) {
    const float* x     = (const float*)d_in[0];
    const float* ctx   = (const float*)d_in[1];
    const float* wq    = (const float*)d_in[2];
    const float* bq    = (const float*)d_in[3];
    const float* wk    = (const float*)d_in[4];
    const float* bk    = (const float*)d_in[5];
    const float* wv    = (const float*)d_in[6];
    const float* bv    = (const float*)d_in[7];
    const float* wo    = (const float*)d_in[8];
    const float* bo    = (const float*)d_in[9];
    const float* w1    = (const float*)d_in[10];
    const float* b1    = (const float*)d_in[11];
    const float* w2    = (const float*)d_in[12];
    const float* b2    = (const float*)d_in[13];
    const float* qn_w  = (const float*)d_in[14];
    const float* qn_b  = (const float*)d_in[15];
    const float* kvn_w = (const float*)d_in[16];
    const float* kvn_b = (const float*)d_in[17];
    const float* pn_w  = (const float*)d_in[18];
    const float* pn_b  = (const float*)d_in[19];
    float* out = (float*)d_out;

#define GETP(name) \
    ushortx* name##p; cudaGetSymbolAddress((void**)&name##p, g_##name)
    GETP(xq); GETP(kv); GETP(q); GETP(k); GETP(v); GETP(o); GETP(hln); GETP(h1);
    GETP(wq); GETP(wk); GETP(wv); GETP(wo); GETP(w1); GETP(w2);
#undef GETP
    float* x1;
    cudaGetSymbolAddress((void**)&x1, g_x1);

    const int GSM128 = 4 * (128 * 80 + 32 * 272);  // 75776
    const int GSM64  = 4 * (64 * 80 + 32 * 272);   // 55296
    const int FSM = 18432 + 2 * 18432;             // 55296
    cudaFuncSetAttribute((const void*)qkv_gemm,
                         cudaFuncAttributeMaxDynamicSharedMemorySize, GSM128);
    cudaFuncSetAttribute((const void*)half_gemm<64, 1, 1, 0, 0>,
                         cudaFuncAttributeMaxDynamicSharedMemorySize, GSM64);
    cudaFuncSetAttribute((const void*)half_gemm<128, 1, 0, 1, 1>,
                         cudaFuncAttributeMaxDynamicSharedMemorySize, GSM128);
    cudaFuncSetAttribute((const void*)flash_kernel,
                         cudaFuncAttributeMaxDynamicSharedMemorySize, FSM);

    // 0+1. fused prologue: both pre-norms + all 6 weight converts, one launch
    prologue_kernel<<<NT + MT + CV_BLOCKS, 256>>>(
        x, qn_w, qn_b, xqp, ctx, kvn_w, kvn_b, kvp,
        wq, wqp, wk, wkp, wv, wvp, wo, wop, w1, w1p, w2, w2p);

    // 2. fused Q/K/V projections
    qkv_gemm<<<dim3(DD / 128, NT / 128, 3), 128, GSM128>>>(
        xqp, kvp, wqp, wkp, wvp, bq, bk, bv, qp, kp, vp);

    // 3. fused attention
    flash_kernel<<<dim3(NT / 128, NH), 128, FSM>>>(qp, kp, vp, op);

    // 4. x1 = o @ wo + bo + x
    half_gemm<64, 1, 1, 0, 0><<<dim3(DD / 128, NT / 64), 128, GSM64>>>(
        op, wop, bo, x, x1, nullptr, DD, DD, DD);

    // 5. MLP
    ln_half_kernel<DD><<<NT, 256>>>(x1, pn_w, pn_b, hlnp);
    half_gemm<128, 1, 0, 1, 1><<<dim3(FF / 128, NT / 128), 128, GSM128>>>(
        hlnp, w1p, b1, nullptr, nullptr, h1p, DD, DD, FF);
    half_gemm<64, 1, 1, 0, 0><<<dim3(DD / 128, NT / 64), 128, GSM64>>>(
        h1p, w2p, b2, x1, out, nullptr, FF, FF, DD);
}